// round 1
// baseline (speedup 1.0000x reference)
#include <cuda_runtime.h>
#include <cuda_bf16.h>
#include <math_constants.h>

// Problem constants
#define N_TOK 4096
#define DIM   1024

// GEMM tiling
#define BM 128
#define BN 128
#define BK 16
#define TM 8
#define TN 8
#define NTHREADS 256
#define APAD 4   // smem row padding for transposed stores

// Scratch (device globals; no allocation allowed)
__device__ float g_q[(size_t)N_TOK * DIM];
__device__ float g_k[(size_t)N_TOK * DIM];
__device__ float g_s[(size_t)N_TOK * N_TOK];

// ---------------------------------------------------------------------------
// NT GEMM: C[M,N] = A[M,K] * B[N,K]^T (+ bias[N] if bias != nullptr)
// A, B row-major, K-contiguous. M,N multiples of 128, K multiple of 16.
// ---------------------------------------------------------------------------
__global__ __launch_bounds__(NTHREADS, 2)
void gemm_nt_bias(const float* __restrict__ A,
                  const float* __restrict__ B,
                  const float* __restrict__ bias,
                  float* __restrict__ C,
                  int M, int N, int K)
{
    __shared__ float As[BK][BM + APAD];
    __shared__ float Bs[BK][BN + APAD];

    const int bx = blockIdx.x;           // N tile
    const int by = blockIdx.y;           // M tile
    const int tid = threadIdx.x;
    const int tx = tid & 15;             // 0..15
    const int ty = tid >> 4;             // 0..15

    const float* Aptr = A + (size_t)by * BM * K;
    const float* Bptr = B + (size_t)bx * BN * K;

    float acc[TM][TN];
#pragma unroll
    for (int i = 0; i < TM; i++)
#pragma unroll
        for (int j = 0; j < TN; j++) acc[i][j] = 0.0f;

    for (int k0 = 0; k0 < K; k0 += BK) {
        // Load A tile (128 rows x 16 cols) = 512 float4, 2 per thread.
#pragma unroll
        for (int i = 0; i < 2; i++) {
            int idx = tid + i * NTHREADS;      // 0..511
            int row = idx >> 2;                // 0..127
            int c4  = idx & 3;                 // 0..3
            float4 v = *(const float4*)(Aptr + (size_t)row * K + k0 + c4 * 4);
            As[c4 * 4 + 0][row] = v.x;
            As[c4 * 4 + 1][row] = v.y;
            As[c4 * 4 + 2][row] = v.z;
            As[c4 * 4 + 3][row] = v.w;
        }
        // Load B tile (128 rows x 16 cols), transposed the same way.
#pragma unroll
        for (int i = 0; i < 2; i++) {
            int idx = tid + i * NTHREADS;
            int row = idx >> 2;
            int c4  = idx & 3;
            float4 v = *(const float4*)(Bptr + (size_t)row * K + k0 + c4 * 4);
            Bs[c4 * 4 + 0][row] = v.x;
            Bs[c4 * 4 + 1][row] = v.y;
            Bs[c4 * 4 + 2][row] = v.z;
            Bs[c4 * 4 + 3][row] = v.w;
        }
        __syncthreads();

#pragma unroll
        for (int k = 0; k < BK; k++) {
            float a[TM], b[TN];
            float4 a0 = *(const float4*)&As[k][ty * TM];
            float4 a1 = *(const float4*)&As[k][ty * TM + 4];
            a[0]=a0.x; a[1]=a0.y; a[2]=a0.z; a[3]=a0.w;
            a[4]=a1.x; a[5]=a1.y; a[6]=a1.z; a[7]=a1.w;
            float4 b0 = *(const float4*)&Bs[k][tx * TN];
            float4 b1 = *(const float4*)&Bs[k][tx * TN + 4];
            b[0]=b0.x; b[1]=b0.y; b[2]=b0.z; b[3]=b0.w;
            b[4]=b1.x; b[5]=b1.y; b[6]=b1.z; b[7]=b1.w;
#pragma unroll
            for (int i = 0; i < TM; i++)
#pragma unroll
                for (int j = 0; j < TN; j++)
                    acc[i][j] = fmaf(a[i], b[j], acc[i][j]);
        }
        __syncthreads();
    }

    // Epilogue
    const int row0 = by * BM + ty * TM;
    const int col0 = bx * BN + tx * TN;
#pragma unroll
    for (int i = 0; i < TM; i++) {
#pragma unroll
        for (int j = 0; j < TN; j += 4) {
            float4 v;
            v.x = acc[i][j + 0];
            v.y = acc[i][j + 1];
            v.z = acc[i][j + 2];
            v.w = acc[i][j + 3];
            if (bias) {
                v.x += bias[col0 + j + 0];
                v.y += bias[col0 + j + 1];
                v.z += bias[col0 + j + 2];
                v.w += bias[col0 + j + 3];
            }
            *(float4*)(C + (size_t)(row0 + i) * N + col0 + j) = v;
        }
    }
}

// ---------------------------------------------------------------------------
// NN GEMM: C[M,N] = A[M,K] * B[K,N]. Row-major. M,N mult of 128, K mult of 16.
// ---------------------------------------------------------------------------
__global__ __launch_bounds__(NTHREADS, 2)
void gemm_nn(const float* __restrict__ A,
             const float* __restrict__ B,
             float* __restrict__ C,
             int M, int N, int K)
{
    __shared__ float As[BK][BM + APAD];
    __shared__ float Bs[BK][BN];

    const int bx = blockIdx.x;           // N tile
    const int by = blockIdx.y;           // M tile
    const int tid = threadIdx.x;
    const int tx = tid & 15;
    const int ty = tid >> 4;

    const float* Aptr = A + (size_t)by * BM * K;
    const float* Bptr = B + (size_t)bx * BN;

    float acc[TM][TN];
#pragma unroll
    for (int i = 0; i < TM; i++)
#pragma unroll
        for (int j = 0; j < TN; j++) acc[i][j] = 0.0f;

    for (int k0 = 0; k0 < K; k0 += BK) {
        // A tile: 128 rows x 16 k, transposed into smem.
#pragma unroll
        for (int i = 0; i < 2; i++) {
            int idx = tid + i * NTHREADS;
            int row = idx >> 2;
            int c4  = idx & 3;
            float4 v = *(const float4*)(Aptr + (size_t)row * K + k0 + c4 * 4);
            As[c4 * 4 + 0][row] = v.x;
            As[c4 * 4 + 1][row] = v.y;
            As[c4 * 4 + 2][row] = v.z;
            As[c4 * 4 + 3][row] = v.w;
        }
        // B tile: 16 k-rows x 128 cols, direct copy (N-contiguous).
#pragma unroll
        for (int i = 0; i < 2; i++) {
            int idx = tid + i * NTHREADS;     // 0..511
            int row = idx >> 5;               // 0..15
            int c4  = idx & 31;               // 0..31
            float4 v = *(const float4*)(Bptr + (size_t)(k0 + row) * N + c4 * 4);
            *(float4*)&Bs[row][c4 * 4] = v;
        }
        __syncthreads();

#pragma unroll
        for (int k = 0; k < BK; k++) {
            float a[TM], b[TN];
            float4 a0 = *(const float4*)&As[k][ty * TM];
            float4 a1 = *(const float4*)&As[k][ty * TM + 4];
            a[0]=a0.x; a[1]=a0.y; a[2]=a0.z; a[3]=a0.w;
            a[4]=a1.x; a[5]=a1.y; a[6]=a1.z; a[7]=a1.w;
            float4 b0 = *(const float4*)&Bs[k][tx * TN];
            float4 b1 = *(const float4*)&Bs[k][tx * TN + 4];
            b[0]=b0.x; b[1]=b0.y; b[2]=b0.z; b[3]=b0.w;
            b[4]=b1.x; b[5]=b1.y; b[6]=b1.z; b[7]=b1.w;
#pragma unroll
            for (int i = 0; i < TM; i++)
#pragma unroll
                for (int j = 0; j < TN; j++)
                    acc[i][j] = fmaf(a[i], b[j], acc[i][j]);
        }
        __syncthreads();
    }

    const int row0 = by * BM + ty * TM;
    const int col0 = bx * BN + tx * TN;
#pragma unroll
    for (int i = 0; i < TM; i++) {
#pragma unroll
        for (int j = 0; j < TN; j += 4) {
            float4 v;
            v.x = acc[i][j + 0];
            v.y = acc[i][j + 1];
            v.z = acc[i][j + 2];
            v.w = acc[i][j + 3];
            *(float4*)(C + (size_t)(row0 + i) * N + col0 + j) = v;
        }
    }
}

// ---------------------------------------------------------------------------
// Row softmax over S[rows, 4096], one block per row, 256 threads.
// Values live in registers (16 per thread): 1 global read + 1 global write.
// ---------------------------------------------------------------------------
__global__ __launch_bounds__(256, 4)
void softmax_rows(float* __restrict__ S)
{
    const int row = blockIdx.x;
    float* r = S + (size_t)row * N_TOK;
    const int tid = threadIdx.x;
    const int lane = tid & 31;
    const int wid = tid >> 5;

    __shared__ float red[32];

    float4 v[4];
    float mx = -CUDART_INF_F;
#pragma unroll
    for (int i = 0; i < 4; i++) {
        v[i] = *(const float4*)(r + (size_t)(tid + i * 256) * 4);
        mx = fmaxf(mx, fmaxf(fmaxf(v[i].x, v[i].y), fmaxf(v[i].z, v[i].w)));
    }
    // block max
#pragma unroll
    for (int o = 16; o > 0; o >>= 1)
        mx = fmaxf(mx, __shfl_xor_sync(0xffffffffu, mx, o));
    if (lane == 0) red[wid] = mx;
    __syncthreads();
    if (wid == 0) {
        float m = (lane < 8) ? red[lane] : -CUDART_INF_F;
#pragma unroll
        for (int o = 4; o > 0; o >>= 1)
            m = fmaxf(m, __shfl_xor_sync(0xffffffffu, m, o));
        if (lane == 0) red[0] = m;
    }
    __syncthreads();
    mx = red[0];
    __syncthreads();

    float sum = 0.0f;
#pragma unroll
    for (int i = 0; i < 4; i++) {
        v[i].x = expf(v[i].x - mx);
        v[i].y = expf(v[i].y - mx);
        v[i].z = expf(v[i].z - mx);
        v[i].w = expf(v[i].w - mx);
        sum += v[i].x + v[i].y + v[i].z + v[i].w;
    }
#pragma unroll
    for (int o = 16; o > 0; o >>= 1)
        sum += __shfl_xor_sync(0xffffffffu, sum, o);
    if (lane == 0) red[wid] = sum;
    __syncthreads();
    if (wid == 0) {
        float s = (lane < 8) ? red[lane] : 0.0f;
#pragma unroll
        for (int o = 4; o > 0; o >>= 1)
            s += __shfl_xor_sync(0xffffffffu, s, o);
        if (lane == 0) red[0] = s;
    }
    __syncthreads();
    const float inv = 1.0f / red[0];

#pragma unroll
    for (int i = 0; i < 4; i++) {
        v[i].x *= inv; v[i].y *= inv; v[i].z *= inv; v[i].w *= inv;
        *(float4*)(r + (size_t)(tid + i * 256) * 4) = v[i];
    }
}

// ---------------------------------------------------------------------------
// Launch
// ---------------------------------------------------------------------------
extern "C" void kernel_launch(void* const* d_in, const int* in_sizes, int n_in,
                              void* d_out, int out_size)
{
    const float* x  = (const float*)d_in[0];   // [4096, 1024]
    const float* Wq = (const float*)d_in[1];   // [1024, 1024]
    const float* bq = (const float*)d_in[2];   // [1024]
    const float* Wk = (const float*)d_in[3];   // [1024, 1024]
    const float* bk = (const float*)d_in[4];   // [1024]
    float* out = (float*)d_out;                // [4096, 1024]

    float *q_ptr, *k_ptr, *s_ptr;
    cudaGetSymbolAddress((void**)&q_ptr, g_q);
    cudaGetSymbolAddress((void**)&k_ptr, g_k);
    cudaGetSymbolAddress((void**)&s_ptr, g_s);

    dim3 block(NTHREADS);

    // q = x @ Wq^T + bq    (M=4096, N=1024, K=1024)
    dim3 grid_proj(DIM / BN, N_TOK / BM);
    gemm_nt_bias<<<grid_proj, block>>>(x, Wq, bq, q_ptr, N_TOK, DIM, DIM);
    // k = x @ Wk^T + bk
    gemm_nt_bias<<<grid_proj, block>>>(x, Wk, bk, k_ptr, N_TOK, DIM, DIM);

    // scores = q @ k^T     (M=4096, N=4096, K=1024)
    dim3 grid_s(N_TOK / BN, N_TOK / BM);
    gemm_nt_bias<<<grid_s, block>>>(q_ptr, k_ptr, nullptr, s_ptr, N_TOK, N_TOK, DIM);

    // softmax rows
    softmax_rows<<<N_TOK, 256>>>(s_ptr);

    // out = attn @ x       (M=4096, N=1024, K=4096)
    dim3 grid_o(DIM / BN, N_TOK / BM);
    gemm_nn<<<grid_o, block>>>(s_ptr, x, out, N_TOK, DIM, N_TOK);
}

// round 3
// speedup vs baseline: 2.4534x; 2.4534x over previous
#include <cuda_runtime.h>
#include <cuda_bf16.h>
#include <math_constants.h>
#include <cstdint>

#define N_TOK 4096
#define DIM   1024

typedef __nv_bfloat16 bf16;

// ---------------------------------------------------------------------------
// Scratch (device globals; no allocation allowed)
// ---------------------------------------------------------------------------
__device__ bf16 g_xh [(size_t)N_TOK * DIM];
__device__ bf16 g_xl [(size_t)N_TOK * DIM];
__device__ bf16 g_xth[(size_t)DIM * N_TOK];   // x^T splits
__device__ bf16 g_xtl[(size_t)DIM * N_TOK];
__device__ bf16 g_wqh[(size_t)DIM * DIM];
__device__ bf16 g_wql[(size_t)DIM * DIM];
__device__ bf16 g_wkh[(size_t)DIM * DIM];
__device__ bf16 g_wkl[(size_t)DIM * DIM];
__device__ bf16 g_qh [(size_t)N_TOK * DIM];
__device__ bf16 g_ql [(size_t)N_TOK * DIM];
__device__ bf16 g_kh [(size_t)N_TOK * DIM];
__device__ bf16 g_kl [(size_t)N_TOK * DIM];
__device__ float g_s [(size_t)N_TOK * N_TOK];
__device__ bf16 g_sh [(size_t)N_TOK * N_TOK];
__device__ bf16 g_sl [(size_t)N_TOK * N_TOK];

// ---------------------------------------------------------------------------
// Helpers
// ---------------------------------------------------------------------------
__device__ __forceinline__ uint32_t smem_to_u32(const void* p) {
    uint32_t a;
    asm("{ .reg .u64 t; cvta.to.shared.u64 t, %1; cvt.u32.u64 %0, t; }"
        : "=r"(a) : "l"(p));
    return a;
}

__device__ __forceinline__ void cp_async16(uint32_t dst, const void* src) {
    asm volatile("cp.async.cg.shared.global [%0], [%1], 16;"
        :: "r"(dst), "l"(src) : "memory");
}
#define CP_COMMIT() asm volatile("cp.async.commit_group;" ::: "memory")
#define CP_WAIT1()  asm volatile("cp.async.wait_group 1;" ::: "memory")

__device__ __forceinline__ void ldmx4(uint32_t r[4], uint32_t addr) {
    asm volatile("ldmatrix.sync.aligned.m8n8.x4.shared.b16 {%0,%1,%2,%3}, [%4];"
        : "=r"(r[0]), "=r"(r[1]), "=r"(r[2]), "=r"(r[3]) : "r"(addr));
}

__device__ __forceinline__ void mma_bf16(float d[4], const uint32_t a[4],
                                         uint32_t b0, uint32_t b1) {
    asm volatile(
        "mma.sync.aligned.m16n8k16.row.col.f32.bf16.bf16.f32 "
        "{%0,%1,%2,%3}, {%4,%5,%6,%7}, {%8,%9}, {%0,%1,%2,%3};"
        : "+f"(d[0]), "+f"(d[1]), "+f"(d[2]), "+f"(d[3])
        : "r"(a[0]), "r"(a[1]), "r"(a[2]), "r"(a[3]), "r"(b0), "r"(b1));
}

__device__ __forceinline__ void split2(float v, bf16& h, bf16& l) {
    h = __float2bfloat16(v);
    l = __float2bfloat16(v - __bfloat162float(h));
}

// ---------------------------------------------------------------------------
// Split-bf16 tensor-core GEMM:  C[M,N] = A[M,K] @ B[N,K]^T (fp32 effective)
// A,B as (hi,lo) bf16 pairs, rows K-contiguous. Block 128x128, BK=64 chunks,
// 8 warps of 64x32, 2-stage cp.async pipeline, SW128 smem swizzle.
// mode 0: C fp32 -> Cf.   mode 1: C + bias -> (Ch, Cl) bf16 split.
// ---------------------------------------------------------------------------
#define TILE_B   16384u          // 128 rows * 128 bytes (one operand, one stage)
#define STAGE_B  (4u * TILE_B)   // Ah, Al, Bh, Bl
#define SMEM_DYN (2u * STAGE_B)  // 128 KB

__global__ __launch_bounds__(256, 1)
void gemm3(const bf16* __restrict__ Ah_, const bf16* __restrict__ Al_,
           const bf16* __restrict__ Bh_, const bf16* __restrict__ Bl_,
           const float* __restrict__ bias,
           float* __restrict__ Cf, bf16* __restrict__ Ch, bf16* __restrict__ Cl,
           int M, int N, int K, int mode)
{
    extern __shared__ char smem_raw[];
    const uint32_t sbase = smem_to_u32(smem_raw);

    const int tid  = threadIdx.x;
    const int w    = tid >> 5;
    const int lane = tid & 31;
    const int bx = blockIdx.x;   // N tile
    const int by = blockIdx.y;   // M tile
    const int wm = (w >> 2) * 64;   // warp m offset in block
    const int wn = (w & 3) * 32;    // warp n offset in block

    const bf16* gAh = Ah_ + (size_t)by * 128 * K;
    const bf16* gAl = Al_ + (size_t)by * 128 * K;
    const bf16* gBh = Bh_ + (size_t)bx * 128 * K;
    const bf16* gBl = Bl_ + (size_t)bx * 128 * K;

    float acc[4][4][4];
#pragma unroll
    for (int i = 0; i < 4; i++)
#pragma unroll
        for (int j = 0; j < 4; j++)
#pragma unroll
            for (int k = 0; k < 4; k++) acc[i][j][k] = 0.0f;

    // Precompute per-thread load geometry: 4 (row,unit) pairs covering
    // 1024 16B-units of one 128x128B tile with 256 threads.
    int   lrow[4];
    uint32_t lso[4];
    size_t lgo[4];
#pragma unroll
    for (int i = 0; i < 4; i++) {
        int idx = tid + i * 256;       // 0..1023
        int row = idx >> 3;            // 0..127
        int u   = idx & 7;             // 0..7 (16B units)
        lrow[i] = row;
        lso[i]  = (uint32_t)row * 128u + (uint32_t)((u ^ (row & 7)) << 4);
        lgo[i]  = (size_t)row * K + (size_t)u * 8;
    }

    const int NC = K >> 6;   // K / 64

    // ---- stage loader (cp.async) ----
    auto load_stage = [&](int c, int s) {
        const size_t kofs = (size_t)c << 6;
        const uint32_t sb = sbase + (uint32_t)s * STAGE_B;
#pragma unroll
        for (int i = 0; i < 4; i++) {
            cp_async16(sb + 0u * TILE_B + lso[i], gAh + lgo[i] + kofs);
            cp_async16(sb + 1u * TILE_B + lso[i], gAl + lgo[i] + kofs);
            cp_async16(sb + 2u * TILE_B + lso[i], gBh + lgo[i] + kofs);
            cp_async16(sb + 3u * TILE_B + lso[i], gBl + lgo[i] + kofs);
        }
    };

    load_stage(0, 0);
    CP_COMMIT();

    const int lr = lane & 15;
    const int lu = lane >> 4;

    for (int c = 0; c < NC; c++) {
        if (c + 1 < NC) load_stage(c + 1, (c + 1) & 1);
        CP_COMMIT();
        CP_WAIT1();
        __syncthreads();

        const uint32_t st  = sbase + (uint32_t)(c & 1) * STAGE_B;
        const uint32_t Ahb = st;
        const uint32_t Alb = st + 1u * TILE_B;
        const uint32_t Bhb = st + 2u * TILE_B;
        const uint32_t Blb = st + 3u * TILE_B;

#pragma unroll
        for (int ks = 0; ks < 4; ks++) {
            uint32_t ah[4][4], al[4][4], bh[2][4], bl[2][4];
#pragma unroll
            for (int mt = 0; mt < 4; mt++) {
                int row = wm + mt * 16 + lr;
                int unit = ks * 2 + lu;
                uint32_t off = (uint32_t)row * 128u
                             + (uint32_t)((unit ^ (row & 7)) << 4);
                ldmx4(ah[mt], Ahb + off);
                ldmx4(al[mt], Alb + off);
            }
#pragma unroll
            for (int nt = 0; nt < 2; nt++) {
                int row = wn + nt * 16 + lr;
                int unit = ks * 2 + lu;
                uint32_t off = (uint32_t)row * 128u
                             + (uint32_t)((unit ^ (row & 7)) << 4);
                ldmx4(bh[nt], Bhb + off);
                ldmx4(bl[nt], Blb + off);
            }
#pragma unroll
            for (int mt = 0; mt < 4; mt++) {
#pragma unroll
                for (int n8 = 0; n8 < 4; n8++) {
                    const int nt = n8 >> 1, sel = n8 & 1;
                    const uint32_t b0h = bh[nt][sel], b1h = bh[nt][sel + 2];
                    const uint32_t b0l = bl[nt][sel], b1l = bl[nt][sel + 2];
                    mma_bf16(acc[mt][n8], ah[mt], b0h, b1h);  // hi*hi
                    mma_bf16(acc[mt][n8], ah[mt], b0l, b1l);  // hi*lo
                    mma_bf16(acc[mt][n8], al[mt], b0h, b1h);  // lo*hi
                }
            }
        }
        __syncthreads();
    }

    // ---- epilogue ----
    const int g  = lane >> 2;
    const int tc = lane & 3;
#pragma unroll
    for (int mt = 0; mt < 4; mt++) {
#pragma unroll
        for (int n8 = 0; n8 < 4; n8++) {
            const int r0 = by * 128 + wm + mt * 16 + g;
            const int r1 = r0 + 8;
            const int col = bx * 128 + wn + n8 * 8 + tc * 2;
            float c0 = acc[mt][n8][0], c1 = acc[mt][n8][1];
            float c2 = acc[mt][n8][2], c3 = acc[mt][n8][3];
            if (mode == 1) {
                const float b0 = bias[col], b1 = bias[col + 1];
                c0 += b0; c1 += b1; c2 += b0; c3 += b1;
                bf16 h0,l0,h1,l1,h2,l2,h3,l3;
                split2(c0, h0, l0); split2(c1, h1, l1);
                split2(c2, h2, l2); split2(c3, h3, l3);
                __nv_bfloat162 hh0; hh0.x = h0; hh0.y = h1;
                __nv_bfloat162 ll0; ll0.x = l0; ll0.y = l1;
                __nv_bfloat162 hh1; hh1.x = h2; hh1.y = h3;
                __nv_bfloat162 ll1; ll1.x = l2; ll1.y = l3;
                *(__nv_bfloat162*)(Ch + (size_t)r0 * N + col) = hh0;
                *(__nv_bfloat162*)(Cl + (size_t)r0 * N + col) = ll0;
                *(__nv_bfloat162*)(Ch + (size_t)r1 * N + col) = hh1;
                *(__nv_bfloat162*)(Cl + (size_t)r1 * N + col) = ll1;
            } else {
                float2 v0; v0.x = c0; v0.y = c1;
                float2 v1; v1.x = c2; v1.y = c3;
                *(float2*)(Cf + (size_t)r0 * N + col) = v0;
                *(float2*)(Cf + (size_t)r1 * N + col) = v1;
            }
        }
    }
}

// ---------------------------------------------------------------------------
// fp32 -> (hi, lo) bf16 split, vectorized x4
// ---------------------------------------------------------------------------
__global__ __launch_bounds__(256)
void split_kernel(const float* __restrict__ in, bf16* __restrict__ oh,
                  bf16* __restrict__ ol, int n4)
{
    int i = blockIdx.x * blockDim.x + threadIdx.x;
    if (i >= n4) return;
    float4 v = ((const float4*)in)[i];
    bf16 h0,l0,h1,l1,h2,l2,h3,l3;
    split2(v.x, h0, l0); split2(v.y, h1, l1);
    split2(v.z, h2, l2); split2(v.w, h3, l3);
    __nv_bfloat162 ha; ha.x = h0; ha.y = h1;
    __nv_bfloat162 hb; hb.x = h2; hb.y = h3;
    __nv_bfloat162 la; la.x = l0; la.y = l1;
    __nv_bfloat162 lb; lb.x = l2; lb.y = l3;
    uint2 hu; hu.x = *(uint32_t*)&ha; hu.y = *(uint32_t*)&hb;
    uint2 lu; lu.x = *(uint32_t*)&la; lu.y = *(uint32_t*)&lb;
    ((uint2*)oh)[i] = hu;
    ((uint2*)ol)[i] = lu;
}

// ---------------------------------------------------------------------------
// x [N_TOK, DIM] fp32 -> xT (hi, lo) bf16 [DIM, N_TOK]
// ---------------------------------------------------------------------------
__global__ __launch_bounds__(256)
void transpose_split(const float* __restrict__ in, bf16* __restrict__ oh,
                     bf16* __restrict__ ol)
{
    __shared__ float t[32][33];
    const int c0 = blockIdx.x * 32;   // column block in x (DIM)
    const int r0 = blockIdx.y * 32;   // row block in x (N_TOK)
    const int tx = threadIdx.x;       // 0..31
    const int ty = threadIdx.y;       // 0..7
#pragma unroll
    for (int j = 0; j < 32; j += 8)
        t[ty + j][tx] = in[(size_t)(r0 + ty + j) * DIM + c0 + tx];
    __syncthreads();
#pragma unroll
    for (int j = 0; j < 32; j += 8) {
        float v = t[tx][ty + j];      // = x[r0+tx][c0+ty+j]
        bf16 h, l;
        split2(v, h, l);
        size_t o = (size_t)(c0 + ty + j) * N_TOK + r0 + tx;
        oh[o] = h;
        ol[o] = l;
    }
}

// ---------------------------------------------------------------------------
// Row softmax over S[4096, 4096] fp32, emitting (hi, lo) bf16 split.
// ---------------------------------------------------------------------------
__global__ __launch_bounds__(256, 4)
void softmax_split(const float* __restrict__ S, bf16* __restrict__ oh,
                   bf16* __restrict__ ol)
{
    const int row = blockIdx.x;
    const float* r = S + (size_t)row * N_TOK;
    const int tid = threadIdx.x;
    const int lane = tid & 31;
    const int wid = tid >> 5;

    __shared__ float red[32];

    float4 v[4];
    float mx = -CUDART_INF_F;
#pragma unroll
    for (int i = 0; i < 4; i++) {
        v[i] = *(const float4*)(r + (size_t)(tid + i * 256) * 4);
        mx = fmaxf(mx, fmaxf(fmaxf(v[i].x, v[i].y), fmaxf(v[i].z, v[i].w)));
    }
#pragma unroll
    for (int o = 16; o > 0; o >>= 1)
        mx = fmaxf(mx, __shfl_xor_sync(0xffffffffu, mx, o));
    if (lane == 0) red[wid] = mx;
    __syncthreads();
    if (wid == 0) {
        float m = (lane < 8) ? red[lane] : -CUDART_INF_F;
#pragma unroll
        for (int o = 4; o > 0; o >>= 1)
            m = fmaxf(m, __shfl_xor_sync(0xffffffffu, m, o));
        if (lane == 0) red[0] = m;
    }
    __syncthreads();
    mx = red[0];
    __syncthreads();

    float sum = 0.0f;
#pragma unroll
    for (int i = 0; i < 4; i++) {
        v[i].x = expf(v[i].x - mx);
        v[i].y = expf(v[i].y - mx);
        v[i].z = expf(v[i].z - mx);
        v[i].w = expf(v[i].w - mx);
        sum += v[i].x + v[i].y + v[i].z + v[i].w;
    }
#pragma unroll
    for (int o = 16; o > 0; o >>= 1)
        sum += __shfl_xor_sync(0xffffffffu, sum, o);
    if (lane == 0) red[wid] = sum;
    __syncthreads();
    if (wid == 0) {
        float s = (lane < 8) ? red[lane] : 0.0f;
#pragma unroll
        for (int o = 4; o > 0; o >>= 1)
            s += __shfl_xor_sync(0xffffffffu, s, o);
        if (lane == 0) red[0] = s;
    }
    __syncthreads();
    const float inv = 1.0f / red[0];

#pragma unroll
    for (int i = 0; i < 4; i++) {
        float a0 = v[i].x * inv, a1 = v[i].y * inv;
        float a2 = v[i].z * inv, a3 = v[i].w * inv;
        bf16 h0,l0,h1,l1,h2,l2,h3,l3;
        split2(a0, h0, l0); split2(a1, h1, l1);
        split2(a2, h2, l2); split2(a3, h3, l3);
        __nv_bfloat162 ha; ha.x = h0; ha.y = h1;
        __nv_bfloat162 hb; hb.x = h2; hb.y = h3;
        __nv_bfloat162 la; la.x = l0; la.y = l1;
        __nv_bfloat162 lb; lb.x = l2; lb.y = l3;
        uint2 hu; hu.x = *(uint32_t*)&ha; hu.y = *(uint32_t*)&hb;
        uint2 lu; lu.x = *(uint32_t*)&la; lu.y = *(uint32_t*)&lb;
        size_t p = (size_t)row * N_TOK + (size_t)(tid + i * 256) * 4;
        *(uint2*)(oh + p) = hu;
        *(uint2*)(ol + p) = lu;
    }
}

// ---------------------------------------------------------------------------
// Launch
// ---------------------------------------------------------------------------
extern "C" void kernel_launch(void* const* d_in, const int* in_sizes, int n_in,
                              void* d_out, int out_size)
{
    const float* x  = (const float*)d_in[0];   // [4096, 1024]
    const float* Wq = (const float*)d_in[1];   // [1024, 1024]
    const float* bq = (const float*)d_in[2];   // [1024]
    const float* Wk = (const float*)d_in[3];   // [1024, 1024]
    const float* bk = (const float*)d_in[4];   // [1024]
    float* out = (float*)d_out;                // [4096, 1024]

    bf16 *xh, *xl, *xth, *xtl, *wqh, *wql, *wkh, *wkl;
    bf16 *qh, *ql, *kh, *kl, *sh, *sl;
    float *s;
    cudaGetSymbolAddress((void**)&xh,  g_xh);
    cudaGetSymbolAddress((void**)&xl,  g_xl);
    cudaGetSymbolAddress((void**)&xth, g_xth);
    cudaGetSymbolAddress((void**)&xtl, g_xtl);
    cudaGetSymbolAddress((void**)&wqh, g_wqh);
    cudaGetSymbolAddress((void**)&wql, g_wql);
    cudaGetSymbolAddress((void**)&wkh, g_wkh);
    cudaGetSymbolAddress((void**)&wkl, g_wkl);
    cudaGetSymbolAddress((void**)&qh,  g_qh);
    cudaGetSymbolAddress((void**)&ql,  g_ql);
    cudaGetSymbolAddress((void**)&kh,  g_kh);
    cudaGetSymbolAddress((void**)&kl,  g_kl);
    cudaGetSymbolAddress((void**)&s,   g_s);
    cudaGetSymbolAddress((void**)&sh,  g_sh);
    cudaGetSymbolAddress((void**)&sl,  g_sl);

    cudaFuncSetAttribute(gemm3, cudaFuncAttributeMaxDynamicSharedMemorySize, SMEM_DYN);

    // Split inputs to bf16 hi/lo
    {
        int n4 = N_TOK * DIM / 4;
        split_kernel<<<(n4 + 255) / 256, 256>>>(x, xh, xl, n4);
        int w4 = DIM * DIM / 4;
        split_kernel<<<(w4 + 255) / 256, 256>>>(Wq, wqh, wql, w4);
        split_kernel<<<(w4 + 255) / 256, 256>>>(Wk, wkh, wkl, w4);
        dim3 tg(DIM / 32, N_TOK / 32);
        transpose_split<<<tg, dim3(32, 8)>>>(x, xth, xtl);
    }

    // q = x @ Wq^T + bq -> split   (M=4096, N=1024, K=1024)
    {
        dim3 g(DIM / 128, N_TOK / 128);
        gemm3<<<g, 256, SMEM_DYN>>>(xh, xl, wqh, wql, bq, nullptr, qh, ql,
                                    N_TOK, DIM, DIM, 1);
        gemm3<<<g, 256, SMEM_DYN>>>(xh, xl, wkh, wkl, bk, nullptr, kh, kl,
                                    N_TOK, DIM, DIM, 1);
    }

    // scores = q @ k^T  (M=N=4096, K=1024), fp32 out
    {
        dim3 g(N_TOK / 128, N_TOK / 128);
        gemm3<<<g, 256, SMEM_DYN>>>(qh, ql, kh, kl, nullptr, s, nullptr, nullptr,
                                    N_TOK, N_TOK, DIM, 0);
    }

    // softmax rows -> attn split
    softmax_split<<<N_TOK, 256>>>(s, sh, sl);

    // out = attn @ x = attn @ (xT)^T   (M=4096, N=1024, K=4096), fp32 out
    {
        dim3 g(DIM / 128, N_TOK / 128);
        gemm3<<<g, 256, SMEM_DYN>>>(sh, sl, xth, xtl, nullptr, out, nullptr, nullptr,
                                    N_TOK, DIM, N_TOK, 0);
    }
}

// round 4
// speedup vs baseline: 2.7579x; 1.1241x over previous
#include <cuda_runtime.h>
#include <cuda_fp16.h>
#include <math_constants.h>
#include <cstdint>

#define N_TOK 4096
#define DIM   1024

typedef __half fp16;

// ---------------------------------------------------------------------------
// Scratch (device globals; no allocation allowed)
// ---------------------------------------------------------------------------
__device__ fp16  g_xh [(size_t)N_TOK * DIM];
__device__ fp16  g_xl [(size_t)N_TOK * DIM];
__device__ fp16  g_xth[(size_t)DIM * N_TOK];   // x^T split
__device__ fp16  g_xtl[(size_t)DIM * N_TOK];
__device__ fp16  g_wqt[(size_t)DIM * DIM];     // Wq^T split
__device__ fp16  g_wqtl[(size_t)DIM * DIM];
__device__ fp16  g_wkt[(size_t)DIM * DIM];     // Wk^T split
__device__ fp16  g_wktl[(size_t)DIM * DIM];
__device__ fp16  g_mth[(size_t)DIM * DIM];     // (Wq^T Wk)^T split
__device__ fp16  g_mtl[(size_t)DIM * DIM];
__device__ fp16  g_th [(size_t)N_TOK * DIM];   // t = x @ M split
__device__ fp16  g_tl [(size_t)N_TOK * DIM];
__device__ float g_s  [(size_t)N_TOK * N_TOK];
__device__ fp16  g_sh [(size_t)N_TOK * N_TOK]; // attn (hi only)
__device__ float g_w  [DIM];
__device__ float g_v  [N_TOK];

// ---------------------------------------------------------------------------
// Helpers
// ---------------------------------------------------------------------------
__device__ __forceinline__ uint32_t smem_to_u32(const void* p) {
    uint32_t a;
    asm("{ .reg .u64 t; cvta.to.shared.u64 t, %1; cvt.u32.u64 %0, t; }"
        : "=r"(a) : "l"(p));
    return a;
}

__device__ __forceinline__ void cp_async16(uint32_t dst, const void* src) {
    asm volatile("cp.async.cg.shared.global [%0], [%1], 16;"
        :: "r"(dst), "l"(src) : "memory");
}
#define CP_COMMIT() asm volatile("cp.async.commit_group;" ::: "memory")
#define CP_WAIT(n)  asm volatile("cp.async.wait_group %0;" :: "n"(n) : "memory")

__device__ __forceinline__ void ldmx4(uint32_t r[4], uint32_t addr) {
    asm volatile("ldmatrix.sync.aligned.m8n8.x4.shared.b16 {%0,%1,%2,%3}, [%4];"
        : "=r"(r[0]), "=r"(r[1]), "=r"(r[2]), "=r"(r[3]) : "r"(addr));
}

__device__ __forceinline__ void mma_f16(float d[4], const uint32_t a[4],
                                        uint32_t b0, uint32_t b1) {
    asm volatile(
        "mma.sync.aligned.m16n8k16.row.col.f32.f16.f16.f32 "
        "{%0,%1,%2,%3}, {%4,%5,%6,%7}, {%8,%9}, {%0,%1,%2,%3};"
        : "+f"(d[0]), "+f"(d[1]), "+f"(d[2]), "+f"(d[3])
        : "r"(a[0]), "r"(a[1]), "r"(a[2]), "r"(a[3]), "r"(b0), "r"(b1));
}

__device__ __forceinline__ void split2h(float v, fp16& h, fp16& l) {
    h = __float2half_rn(v);
    l = __float2half_rn(v - __half2float(h));
}

// ---------------------------------------------------------------------------
// 3-pass split-fp16 GEMM: C[M,N] = A[M,K] @ B[N,K]^T  (fp32 effective)
// Block 128x128, BK=64, 8 warps (64x32), 3-stage cp.async pipeline.
// Cf != null: fp32 out.  else: (Ch, Cl) fp16 split out, +bias if bias != null.
// ---------------------------------------------------------------------------
#define TILE_B   16384u
#define STG3_B   (4u * TILE_B)
#define SMEM3    (3u * STG3_B)    // 192 KB

__global__ __launch_bounds__(256, 1)
void gemm3p(const fp16* __restrict__ Ah_, const fp16* __restrict__ Al_,
            const fp16* __restrict__ Bh_, const fp16* __restrict__ Bl_,
            const float* __restrict__ bias,
            float* __restrict__ Cf, fp16* __restrict__ Ch, fp16* __restrict__ Cl,
            int M, int N, int K)
{
    extern __shared__ char smem_raw[];
    const uint32_t sbase = smem_to_u32(smem_raw);

    const int tid  = threadIdx.x;
    const int w    = tid >> 5;
    const int lane = tid & 31;
    const int bx = blockIdx.x, by = blockIdx.y;
    const int wm = (w >> 2) * 64;
    const int wn = (w & 3) * 32;

    const fp16* gAh = Ah_ + (size_t)by * 128 * K;
    const fp16* gAl = Al_ + (size_t)by * 128 * K;
    const fp16* gBh = Bh_ + (size_t)bx * 128 * K;
    const fp16* gBl = Bl_ + (size_t)bx * 128 * K;

    float acc[4][4][4];
#pragma unroll
    for (int i = 0; i < 4; i++)
#pragma unroll
        for (int j = 0; j < 4; j++)
#pragma unroll
            for (int k = 0; k < 4; k++) acc[i][j][k] = 0.0f;

    uint32_t lso[4];
    size_t lgo[4];
#pragma unroll
    for (int i = 0; i < 4; i++) {
        int idx = tid + i * 256;
        int row = idx >> 3;
        int u   = idx & 7;
        lso[i] = (uint32_t)row * 128u + (uint32_t)((u ^ (row & 7)) << 4);
        lgo[i] = (size_t)row * K + (size_t)u * 8;
    }

    const int NC = K >> 6;

    auto load_stage = [&](int c, int s) {
        const size_t kofs = (size_t)c << 6;
        const uint32_t sb = sbase + (uint32_t)s * STG3_B;
#pragma unroll
        for (int i = 0; i < 4; i++) {
            cp_async16(sb + 0u * TILE_B + lso[i], gAh + lgo[i] + kofs);
            cp_async16(sb + 1u * TILE_B + lso[i], gAl + lgo[i] + kofs);
            cp_async16(sb + 2u * TILE_B + lso[i], gBh + lgo[i] + kofs);
            cp_async16(sb + 3u * TILE_B + lso[i], gBl + lgo[i] + kofs);
        }
    };

    load_stage(0, 0); CP_COMMIT();
    if (NC > 1) load_stage(1, 1);
    CP_COMMIT();

    const int lr = lane & 15;
    const int lu = lane >> 4;

    for (int c = 0; c < NC; c++) {
        if (c + 2 < NC) load_stage(c + 2, (c + 2) % 3);
        CP_COMMIT();
        CP_WAIT(2);
        __syncthreads();

        const uint32_t st  = sbase + (uint32_t)(c % 3) * STG3_B;
        const uint32_t Ahb = st;
        const uint32_t Alb = st + 1u * TILE_B;
        const uint32_t Bhb = st + 2u * TILE_B;
        const uint32_t Blb = st + 3u * TILE_B;

#pragma unroll
        for (int ks = 0; ks < 4; ks++) {
            uint32_t ah[4][4], al[4][4], bh[2][4], bl[2][4];
#pragma unroll
            for (int mt = 0; mt < 4; mt++) {
                int row = wm + mt * 16 + lr;
                int unit = ks * 2 + lu;
                uint32_t off = (uint32_t)row * 128u
                             + (uint32_t)((unit ^ (row & 7)) << 4);
                ldmx4(ah[mt], Ahb + off);
                ldmx4(al[mt], Alb + off);
            }
#pragma unroll
            for (int nt = 0; nt < 2; nt++) {
                int row = wn + nt * 16 + lr;
                int unit = ks * 2 + lu;
                uint32_t off = (uint32_t)row * 128u
                             + (uint32_t)((unit ^ (row & 7)) << 4);
                ldmx4(bh[nt], Bhb + off);
                ldmx4(bl[nt], Blb + off);
            }
#pragma unroll
            for (int mt = 0; mt < 4; mt++) {
#pragma unroll
                for (int n8 = 0; n8 < 4; n8++) {
                    const int nt = n8 >> 1, sel = n8 & 1;
                    const uint32_t b0h = bh[nt][sel], b1h = bh[nt][sel + 2];
                    const uint32_t b0l = bl[nt][sel], b1l = bl[nt][sel + 2];
                    mma_f16(acc[mt][n8], ah[mt], b0h, b1h);
                    mma_f16(acc[mt][n8], ah[mt], b0l, b1l);
                    mma_f16(acc[mt][n8], al[mt], b0h, b1h);
                }
            }
        }
        __syncthreads();
    }

    const int g  = lane >> 2;
    const int tc = lane & 3;
#pragma unroll
    for (int mt = 0; mt < 4; mt++) {
#pragma unroll
        for (int n8 = 0; n8 < 4; n8++) {
            const int r0 = by * 128 + wm + mt * 16 + g;
            const int r1 = r0 + 8;
            const int col = bx * 128 + wn + n8 * 8 + tc * 2;
            float c0 = acc[mt][n8][0], c1 = acc[mt][n8][1];
            float c2 = acc[mt][n8][2], c3 = acc[mt][n8][3];
            if (Cf) {
                float2 v0; v0.x = c0; v0.y = c1;
                float2 v1; v1.x = c2; v1.y = c3;
                *(float2*)(Cf + (size_t)r0 * N + col) = v0;
                *(float2*)(Cf + (size_t)r1 * N + col) = v1;
            } else {
                if (bias) {
                    const float b0 = bias[col], b1 = bias[col + 1];
                    c0 += b0; c1 += b1; c2 += b0; c3 += b1;
                }
                fp16 h0,l0,h1,l1,h2,l2,h3,l3;
                split2h(c0, h0, l0); split2h(c1, h1, l1);
                split2h(c2, h2, l2); split2h(c3, h3, l3);
                __half2 hh0 = __halves2half2(h0, h1);
                __half2 ll0 = __halves2half2(l0, l1);
                __half2 hh1 = __halves2half2(h2, h3);
                __half2 ll1 = __halves2half2(l2, l3);
                *(__half2*)(Ch + (size_t)r0 * N + col) = hh0;
                *(__half2*)(Cl + (size_t)r0 * N + col) = ll0;
                *(__half2*)(Ch + (size_t)r1 * N + col) = hh1;
                *(__half2*)(Cl + (size_t)r1 * N + col) = ll1;
            }
        }
    }
}

// ---------------------------------------------------------------------------
// 2-pass GEMM: C[M,N] = A[M,K] @ (Bh+Bl)[N,K]^T, A plain fp16 (no lo split).
// 4-stage cp.async pipeline (3 tiles/stage). fp32 out.
// ---------------------------------------------------------------------------
#define STG2_B (3u * TILE_B)
#define SMEM2  (4u * STG2_B)     // 192 KB

__global__ __launch_bounds__(256, 1)
void gemm2p(const fp16* __restrict__ Ah_,
            const fp16* __restrict__ Bh_, const fp16* __restrict__ Bl_,
            float* __restrict__ Cf, int M, int N, int K)
{
    extern __shared__ char smem_raw[];
    const uint32_t sbase = smem_to_u32(smem_raw);

    const int tid  = threadIdx.x;
    const int w    = tid >> 5;
    const int lane = tid & 31;
    const int bx = blockIdx.x, by = blockIdx.y;
    const int wm = (w >> 2) * 64;
    const int wn = (w & 3) * 32;

    const fp16* gAh = Ah_ + (size_t)by * 128 * K;
    const fp16* gBh = Bh_ + (size_t)bx * 128 * K;
    const fp16* gBl = Bl_ + (size_t)bx * 128 * K;

    float acc[4][4][4];
#pragma unroll
    for (int i = 0; i < 4; i++)
#pragma unroll
        for (int j = 0; j < 4; j++)
#pragma unroll
            for (int k = 0; k < 4; k++) acc[i][j][k] = 0.0f;

    uint32_t lso[4];
    size_t lgo[4];
#pragma unroll
    for (int i = 0; i < 4; i++) {
        int idx = tid + i * 256;
        int row = idx >> 3;
        int u   = idx & 7;
        lso[i] = (uint32_t)row * 128u + (uint32_t)((u ^ (row & 7)) << 4);
        lgo[i] = (size_t)row * K + (size_t)u * 8;
    }

    const int NC = K >> 6;

    auto load_stage = [&](int c, int s) {
        const size_t kofs = (size_t)c << 6;
        const uint32_t sb = sbase + (uint32_t)s * STG2_B;
#pragma unroll
        for (int i = 0; i < 4; i++) {
            cp_async16(sb + 0u * TILE_B + lso[i], gAh + lgo[i] + kofs);
            cp_async16(sb + 1u * TILE_B + lso[i], gBh + lgo[i] + kofs);
            cp_async16(sb + 2u * TILE_B + lso[i], gBl + lgo[i] + kofs);
        }
    };

    load_stage(0, 0); CP_COMMIT();
    if (NC > 1) load_stage(1, 1);
    CP_COMMIT();
    if (NC > 2) load_stage(2, 2);
    CP_COMMIT();

    const int lr = lane & 15;
    const int lu = lane >> 4;

    for (int c = 0; c < NC; c++) {
        if (c + 3 < NC) load_stage(c + 3, (c + 3) & 3);
        CP_COMMIT();
        CP_WAIT(3);
        __syncthreads();

        const uint32_t st  = sbase + (uint32_t)(c & 3) * STG2_B;
        const uint32_t Ahb = st;
        const uint32_t Bhb = st + 1u * TILE_B;
        const uint32_t Blb = st + 2u * TILE_B;

#pragma unroll
        for (int ks = 0; ks < 4; ks++) {
            uint32_t ah[4][4], bh[2][4], bl[2][4];
#pragma unroll
            for (int mt = 0; mt < 4; mt++) {
                int row = wm + mt * 16 + lr;
                int unit = ks * 2 + lu;
                uint32_t off = (uint32_t)row * 128u
                             + (uint32_t)((unit ^ (row & 7)) << 4);
                ldmx4(ah[mt], Ahb + off);
            }
#pragma unroll
            for (int nt = 0; nt < 2; nt++) {
                int row = wn + nt * 16 + lr;
                int unit = ks * 2 + lu;
                uint32_t off = (uint32_t)row * 128u
                             + (uint32_t)((unit ^ (row & 7)) << 4);
                ldmx4(bh[nt], Bhb + off);
                ldmx4(bl[nt], Blb + off);
            }
#pragma unroll
            for (int mt = 0; mt < 4; mt++) {
#pragma unroll
                for (int n8 = 0; n8 < 4; n8++) {
                    const int nt = n8 >> 1, sel = n8 & 1;
                    mma_f16(acc[mt][n8], ah[mt], bh[nt][sel], bh[nt][sel + 2]);
                    mma_f16(acc[mt][n8], ah[mt], bl[nt][sel], bl[nt][sel + 2]);
                }
            }
        }
        __syncthreads();
    }

    const int g  = lane >> 2;
    const int tc = lane & 3;
#pragma unroll
    for (int mt = 0; mt < 4; mt++) {
#pragma unroll
        for (int n8 = 0; n8 < 4; n8++) {
            const int r0 = by * 128 + wm + mt * 16 + g;
            const int r1 = r0 + 8;
            const int col = bx * 128 + wn + n8 * 8 + tc * 2;
            float2 v0; v0.x = acc[mt][n8][0]; v0.y = acc[mt][n8][1];
            float2 v1; v1.x = acc[mt][n8][2]; v1.y = acc[mt][n8][3];
            *(float2*)(Cf + (size_t)r0 * N + col) = v0;
            *(float2*)(Cf + (size_t)r1 * N + col) = v1;
        }
    }
}

// ---------------------------------------------------------------------------
// fp32 -> (hi, lo) fp16 split, vectorized x4
// ---------------------------------------------------------------------------
__global__ __launch_bounds__(256)
void split_h(const float* __restrict__ in, fp16* __restrict__ oh,
             fp16* __restrict__ ol, int n4)
{
    int i = blockIdx.x * blockDim.x + threadIdx.x;
    if (i >= n4) return;
    float4 v = ((const float4*)in)[i];
    fp16 h0,l0,h1,l1,h2,l2,h3,l3;
    split2h(v.x, h0, l0); split2h(v.y, h1, l1);
    split2h(v.z, h2, l2); split2h(v.w, h3, l3);
    __half2 ha = __halves2half2(h0, h1), hb = __halves2half2(h2, h3);
    __half2 la = __halves2half2(l0, l1), lb = __halves2half2(l2, l3);
    uint2 hu; hu.x = *(uint32_t*)&ha; hu.y = *(uint32_t*)&hb;
    uint2 lu; lu.x = *(uint32_t*)&la; lu.y = *(uint32_t*)&lb;
    ((uint2*)oh)[i] = hu;
    ((uint2*)ol)[i] = lu;
}

// ---------------------------------------------------------------------------
// in [R, C] fp32 -> out [C, R] fp16 (hi, lo) split. grid (C/32, R/32), 32x8.
// ---------------------------------------------------------------------------
__global__ __launch_bounds__(256)
void transpose_split_h(const float* __restrict__ in, fp16* __restrict__ oh,
                       fp16* __restrict__ ol, int R, int C)
{
    __shared__ float t[32][33];
    const int c0 = blockIdx.x * 32;
    const int r0 = blockIdx.y * 32;
    const int tx = threadIdx.x;
    const int ty = threadIdx.y;
#pragma unroll
    for (int j = 0; j < 32; j += 8)
        t[ty + j][tx] = in[(size_t)(r0 + ty + j) * C + c0 + tx];
    __syncthreads();
#pragma unroll
    for (int j = 0; j < 32; j += 8) {
        float v = t[tx][ty + j];
        fp16 h, l;
        split2h(v, h, l);
        size_t o = (size_t)(c0 + ty + j) * R + r0 + tx;
        oh[o] = h;
        ol[o] = l;
    }
}

// ---------------------------------------------------------------------------
// w[e] = sum_a bq[a] * Wk[a, e]   (Wk row-major [DIM, DIM])
// ---------------------------------------------------------------------------
__global__ __launch_bounds__(256)
void wvec(const float* __restrict__ Wk, const float* __restrict__ bq,
          float* __restrict__ w)
{
    int e = blockIdx.x * 256 + threadIdx.x;
    float s = 0.0f;
    for (int a = 0; a < DIM; a++)
        s += bq[a] * Wk[(size_t)a * DIM + e];
    w[e] = s;
}

// ---------------------------------------------------------------------------
// v[i] = sum_d x[i, d] * w[d]   — one warp per row
// ---------------------------------------------------------------------------
__global__ __launch_bounds__(256)
void vvec(const float* __restrict__ x, const float* __restrict__ w,
          float* __restrict__ v)
{
    const int wid = threadIdx.x >> 5;
    const int lane = threadIdx.x & 31;
    const int row = blockIdx.x * 8 + wid;
    const float* xr = x + (size_t)row * DIM;
    float s = 0.0f;
#pragma unroll
    for (int it = 0; it < 8; it++) {
        int d = (it * 32 + lane) * 4;
        float4 a = *(const float4*)(xr + d);
        float4 b = *(const float4*)(w + d);
        s += a.x * b.x + a.y * b.y + a.z * b.z + a.w * b.w;
    }
#pragma unroll
    for (int o = 16; o > 0; o >>= 1)
        s += __shfl_xor_sync(0xffffffffu, s, o);
    if (lane == 0) v[row] = s;
}

// ---------------------------------------------------------------------------
// softmax over rows of (S + 1*v^T), emit plain fp16 attn.
// ---------------------------------------------------------------------------
__global__ __launch_bounds__(256, 4)
void softmax_v(const float* __restrict__ S, const float* __restrict__ vcol,
               fp16* __restrict__ oh)
{
    const int row = blockIdx.x;
    const float* r = S + (size_t)row * N_TOK;
    const int tid = threadIdx.x;
    const int lane = tid & 31;
    const int wid = tid >> 5;

    __shared__ float red[32];

    float4 v[4];
    float mx = -CUDART_INF_F;
#pragma unroll
    for (int i = 0; i < 4; i++) {
        size_t p = (size_t)(tid + i * 256) * 4;
        v[i] = *(const float4*)(r + p);
        float4 vv = *(const float4*)(vcol + p);
        v[i].x += vv.x; v[i].y += vv.y; v[i].z += vv.z; v[i].w += vv.w;
        mx = fmaxf(mx, fmaxf(fmaxf(v[i].x, v[i].y), fmaxf(v[i].z, v[i].w)));
    }
#pragma unroll
    for (int o = 16; o > 0; o >>= 1)
        mx = fmaxf(mx, __shfl_xor_sync(0xffffffffu, mx, o));
    if (lane == 0) red[wid] = mx;
    __syncthreads();
    if (wid == 0) {
        float m = (lane < 8) ? red[lane] : -CUDART_INF_F;
#pragma unroll
        for (int o = 4; o > 0; o >>= 1)
            m = fmaxf(m, __shfl_xor_sync(0xffffffffu, m, o));
        if (lane == 0) red[0] = m;
    }
    __syncthreads();
    mx = red[0];
    __syncthreads();

    float sum = 0.0f;
#pragma unroll
    for (int i = 0; i < 4; i++) {
        v[i].x = expf(v[i].x - mx);
        v[i].y = expf(v[i].y - mx);
        v[i].z = expf(v[i].z - mx);
        v[i].w = expf(v[i].w - mx);
        sum += v[i].x + v[i].y + v[i].z + v[i].w;
    }
#pragma unroll
    for (int o = 16; o > 0; o >>= 1)
        sum += __shfl_xor_sync(0xffffffffu, sum, o);
    if (lane == 0) red[wid] = sum;
    __syncthreads();
    if (wid == 0) {
        float s = (lane < 8) ? red[lane] : 0.0f;
#pragma unroll
        for (int o = 4; o > 0; o >>= 1)
            s += __shfl_xor_sync(0xffffffffu, s, o);
        if (lane == 0) red[0] = s;
    }
    __syncthreads();
    const float inv = 1.0f / red[0];

#pragma unroll
    for (int i = 0; i < 4; i++) {
        __half2 a = __halves2half2(__float2half_rn(v[i].x * inv),
                                   __float2half_rn(v[i].y * inv));
        __half2 b = __halves2half2(__float2half_rn(v[i].z * inv),
                                   __float2half_rn(v[i].w * inv));
        uint2 u; u.x = *(uint32_t*)&a; u.y = *(uint32_t*)&b;
        size_t p = (size_t)row * N_TOK + (size_t)(tid + i * 256) * 4;
        *(uint2*)(oh + p) = u;
    }
}

// ---------------------------------------------------------------------------
// Launch
// ---------------------------------------------------------------------------
extern "C" void kernel_launch(void* const* d_in, const int* in_sizes, int n_in,
                              void* d_out, int out_size)
{
    const float* x  = (const float*)d_in[0];   // [4096, 1024]
    const float* Wq = (const float*)d_in[1];   // [1024, 1024]
    const float* bq = (const float*)d_in[2];   // [1024]
    const float* Wk = (const float*)d_in[3];   // [1024, 1024]
    const float* bk = (const float*)d_in[4];   // [1024]  (unused: cancels in softmax)
    float* out = (float*)d_out;                // [4096, 1024]
    (void)bk;

    fp16 *xh, *xl, *xth, *xtl, *wqt, *wqtl, *wkt, *wktl, *mth, *mtl, *th, *tl, *sh;
    float *s, *wv, *vv;
    cudaGetSymbolAddress((void**)&xh,   g_xh);
    cudaGetSymbolAddress((void**)&xl,   g_xl);
    cudaGetSymbolAddress((void**)&xth,  g_xth);
    cudaGetSymbolAddress((void**)&xtl,  g_xtl);
    cudaGetSymbolAddress((void**)&wqt,  g_wqt);
    cudaGetSymbolAddress((void**)&wqtl, g_wqtl);
    cudaGetSymbolAddress((void**)&wkt,  g_wkt);
    cudaGetSymbolAddress((void**)&wktl, g_wktl);
    cudaGetSymbolAddress((void**)&mth,  g_mth);
    cudaGetSymbolAddress((void**)&mtl,  g_mtl);
    cudaGetSymbolAddress((void**)&th,   g_th);
    cudaGetSymbolAddress((void**)&tl,   g_tl);
    cudaGetSymbolAddress((void**)&sh,   g_sh);
    cudaGetSymbolAddress((void**)&s,    g_s);
    cudaGetSymbolAddress((void**)&wv,   g_w);
    cudaGetSymbolAddress((void**)&vv,   g_v);

    cudaFuncSetAttribute(gemm3p, cudaFuncAttributeMaxDynamicSharedMemorySize, SMEM3);
    cudaFuncSetAttribute(gemm2p, cudaFuncAttributeMaxDynamicSharedMemorySize, SMEM2);

    // Prep: splits, transposes, bias vectors
    {
        int n4 = N_TOK * DIM / 4;
        split_h<<<(n4 + 255) / 256, 256>>>(x, xh, xl, n4);
        transpose_split_h<<<dim3(DIM / 32, N_TOK / 32), dim3(32, 8)>>>(x, xth, xtl, N_TOK, DIM);
        transpose_split_h<<<dim3(DIM / 32, DIM / 32), dim3(32, 8)>>>(Wq, wqt, wqtl, DIM, DIM);
        transpose_split_h<<<dim3(DIM / 32, DIM / 32), dim3(32, 8)>>>(Wk, wkt, wktl, DIM, DIM);
        wvec<<<DIM / 256, 256>>>(Wk, bq, wv);
        vvec<<<N_TOK / 8, 256>>>(x, wv, vv);
    }

    // Mt = Wk^T @ Wq  (= (Wq^T Wk)^T), split out. M=N=K=1024
    gemm3p<<<dim3(DIM / 128, DIM / 128), 256, SMEM3>>>(
        wkt, wktl, wqt, wqtl, nullptr, nullptr, mth, mtl, DIM, DIM, DIM);

    // t = x @ M  (A=x split, B=Mt split), split out. M=4096,N=1024,K=1024
    gemm3p<<<dim3(DIM / 128, N_TOK / 128), 256, SMEM3>>>(
        xh, xl, mth, mtl, nullptr, nullptr, th, tl, N_TOK, DIM, DIM);

    // scores = t @ x^T, fp32 out. M=N=4096, K=1024
    gemm3p<<<dim3(N_TOK / 128, N_TOK / 128), 256, SMEM3>>>(
        th, tl, xh, xl, nullptr, s, nullptr, nullptr, N_TOK, N_TOK, DIM);

    // softmax(scores + 1*v^T) -> attn fp16
    softmax_v<<<N_TOK, 256>>>(s, vv, sh);

    // out = attn @ x  (A=attn plain, B=xT split), 2-pass. M=4096,N=1024,K=4096
    gemm2p<<<dim3(DIM / 128, N_TOK / 128), 256, SMEM2>>>(
        sh, xth, xtl, out, N_TOK, DIM, N_TOK);
}

// round 5
// speedup vs baseline: 2.7989x; 1.0149x over previous
#include <cuda_runtime.h>
#include <cuda_fp16.h>
#include <math_constants.h>
#include <cstdint>

#define N_TOK 4096
#define DIM   1024

typedef __half fp16;

// ---------------------------------------------------------------------------
// Scratch (device globals; no allocation allowed)
// ---------------------------------------------------------------------------
__device__ fp16  g_xh [(size_t)N_TOK * DIM];
__device__ fp16  g_xl [(size_t)N_TOK * DIM];
__device__ fp16  g_xth[(size_t)DIM * N_TOK];   // x^T split
__device__ fp16  g_xtl[(size_t)DIM * N_TOK];
__device__ fp16  g_wqt[(size_t)DIM * DIM];     // Wq^T split
__device__ fp16  g_wqtl[(size_t)DIM * DIM];
__device__ fp16  g_wkt[(size_t)DIM * DIM];     // Wk^T split
__device__ fp16  g_wktl[(size_t)DIM * DIM];
__device__ fp16  g_mth[(size_t)DIM * DIM];     // (Wq^T Wk)^T split
__device__ fp16  g_mtl[(size_t)DIM * DIM];
__device__ fp16  g_th [(size_t)N_TOK * DIM];   // t = x @ M split
__device__ fp16  g_tl [(size_t)N_TOK * DIM];
__device__ float g_s  [(size_t)N_TOK * N_TOK];
__device__ fp16  g_sh [(size_t)N_TOK * N_TOK]; // attn (hi only)
__device__ float g_w  [DIM];
__device__ float g_v  [N_TOK];

// ---------------------------------------------------------------------------
// Helpers
// ---------------------------------------------------------------------------
__device__ __forceinline__ uint32_t smem_to_u32(const void* p) {
    uint32_t a;
    asm("{ .reg .u64 t; cvta.to.shared.u64 t, %1; cvt.u32.u64 %0, t; }"
        : "=r"(a) : "l"(p));
    return a;
}

__device__ __forceinline__ void cp_async16(uint32_t dst, const void* src) {
    asm volatile("cp.async.cg.shared.global [%0], [%1], 16;"
        :: "r"(dst), "l"(src) : "memory");
}
#define CP_COMMIT() asm volatile("cp.async.commit_group;" ::: "memory")
#define CP_WAIT(n)  asm volatile("cp.async.wait_group %0;" :: "n"(n) : "memory")

__device__ __forceinline__ void ldmx4(uint32_t r[4], uint32_t addr) {
    asm volatile("ldmatrix.sync.aligned.m8n8.x4.shared.b16 {%0,%1,%2,%3}, [%4];"
        : "=r"(r[0]), "=r"(r[1]), "=r"(r[2]), "=r"(r[3]) : "r"(addr));
}

__device__ __forceinline__ void mma_f16(float d[4], const uint32_t a[4],
                                        uint32_t b0, uint32_t b1) {
    asm volatile(
        "mma.sync.aligned.m16n8k16.row.col.f32.f16.f16.f32 "
        "{%0,%1,%2,%3}, {%4,%5,%6,%7}, {%8,%9}, {%0,%1,%2,%3};"
        : "+f"(d[0]), "+f"(d[1]), "+f"(d[2]), "+f"(d[3])
        : "r"(a[0]), "r"(a[1]), "r"(a[2]), "r"(a[3]), "r"(b0), "r"(b1));
}

__device__ __forceinline__ void split2h(float v, fp16& h, fp16& l) {
    h = __float2half_rn(v);
    l = __float2half_rn(v - __half2float(h));
}

// ---------------------------------------------------------------------------
// 3-pass split-fp16 GEMM: C[M,N] = A[M,K] @ B[N,K]^T  (fp32 effective)
// Block 128x128, BK=64, 16 warps (32x32 warp tiles), 3-stage cp.async.
// Cf != null: fp32 out.  else: (Ch, Cl) fp16 split out, +bias if bias != null.
// ---------------------------------------------------------------------------
#define TILE_B   16384u
#define STG3_B   (4u * TILE_B)
#define SMEM3    (3u * STG3_B)    // 192 KB
#define NTH      512

__global__ __launch_bounds__(NTH, 1)
void gemm3p(const fp16* __restrict__ Ah_, const fp16* __restrict__ Al_,
            const fp16* __restrict__ Bh_, const fp16* __restrict__ Bl_,
            const float* __restrict__ bias,
            float* __restrict__ Cf, fp16* __restrict__ Ch, fp16* __restrict__ Cl,
            int M, int N, int K)
{
    extern __shared__ char smem_raw[];
    const uint32_t sbase = smem_to_u32(smem_raw);

    const int tid  = threadIdx.x;
    const int w    = tid >> 5;
    const int lane = tid & 31;
    const int bx = blockIdx.x, by = blockIdx.y;
    const int wm = (w >> 2) * 32;    // 4 m-strips of 32
    const int wn = (w & 3) * 32;     // 4 n-strips of 32

    const fp16* gAh = Ah_ + (size_t)by * 128 * K;
    const fp16* gAl = Al_ + (size_t)by * 128 * K;
    const fp16* gBh = Bh_ + (size_t)bx * 128 * K;
    const fp16* gBl = Bl_ + (size_t)bx * 128 * K;

    float acc[2][4][4];
#pragma unroll
    for (int i = 0; i < 2; i++)
#pragma unroll
        for (int j = 0; j < 4; j++)
#pragma unroll
            for (int k = 0; k < 4; k++) acc[i][j][k] = 0.0f;

    // Loader geometry: 1024 16B-units per tile, 512 threads -> 2 per thread.
    uint32_t lso[2];
    size_t lgo[2];
#pragma unroll
    for (int i = 0; i < 2; i++) {
        int idx = tid + i * NTH;
        int row = idx >> 3;
        int u   = idx & 7;
        lso[i] = (uint32_t)row * 128u + (uint32_t)((u ^ (row & 7)) << 4);
        lgo[i] = (size_t)row * K + (size_t)u * 8;
    }

    const int NC = K >> 6;

    auto load_stage = [&](int c, int s) {
        const size_t kofs = (size_t)c << 6;
        const uint32_t sb = sbase + (uint32_t)s * STG3_B;
#pragma unroll
        for (int i = 0; i < 2; i++) {
            cp_async16(sb + 0u * TILE_B + lso[i], gAh + lgo[i] + kofs);
            cp_async16(sb + 1u * TILE_B + lso[i], gAl + lgo[i] + kofs);
            cp_async16(sb + 2u * TILE_B + lso[i], gBh + lgo[i] + kofs);
            cp_async16(sb + 3u * TILE_B + lso[i], gBl + lgo[i] + kofs);
        }
    };

    load_stage(0, 0); CP_COMMIT();
    if (NC > 1) load_stage(1, 1);
    CP_COMMIT();

    const int lr = lane & 15;
    const int lu = lane >> 4;

    for (int c = 0; c < NC; c++) {
        if (c + 2 < NC) load_stage(c + 2, (c + 2) % 3);
        CP_COMMIT();
        CP_WAIT(2);
        __syncthreads();

        const uint32_t st  = sbase + (uint32_t)(c % 3) * STG3_B;
        const uint32_t Ahb = st;
        const uint32_t Alb = st + 1u * TILE_B;
        const uint32_t Bhb = st + 2u * TILE_B;
        const uint32_t Blb = st + 3u * TILE_B;

#pragma unroll
        for (int ks = 0; ks < 4; ks++) {
            uint32_t ah[2][4], al[2][4], bh[2][4], bl[2][4];
            const int unit = ks * 2 + lu;
#pragma unroll
            for (int mt = 0; mt < 2; mt++) {
                int row = wm + mt * 16 + lr;
                uint32_t off = (uint32_t)row * 128u
                             + (uint32_t)((unit ^ (row & 7)) << 4);
                ldmx4(ah[mt], Ahb + off);
                ldmx4(al[mt], Alb + off);
            }
#pragma unroll
            for (int nt = 0; nt < 2; nt++) {
                int row = wn + nt * 16 + lr;
                uint32_t off = (uint32_t)row * 128u
                             + (uint32_t)((unit ^ (row & 7)) << 4);
                ldmx4(bh[nt], Bhb + off);
                ldmx4(bl[nt], Blb + off);
            }
#pragma unroll
            for (int mt = 0; mt < 2; mt++) {
#pragma unroll
                for (int n8 = 0; n8 < 4; n8++) {
                    const int nt = n8 >> 1, sel = n8 & 1;
                    const uint32_t b0h = bh[nt][sel], b1h = bh[nt][sel + 2];
                    const uint32_t b0l = bl[nt][sel], b1l = bl[nt][sel + 2];
                    mma_f16(acc[mt][n8], ah[mt], b0h, b1h);
                    mma_f16(acc[mt][n8], ah[mt], b0l, b1l);
                    mma_f16(acc[mt][n8], al[mt], b0h, b1h);
                }
            }
        }
        __syncthreads();
    }

    const int g  = lane >> 2;
    const int tc = lane & 3;
#pragma unroll
    for (int mt = 0; mt < 2; mt++) {
#pragma unroll
        for (int n8 = 0; n8 < 4; n8++) {
            const int r0 = by * 128 + wm + mt * 16 + g;
            const int r1 = r0 + 8;
            const int col = bx * 128 + wn + n8 * 8 + tc * 2;
            float c0 = acc[mt][n8][0], c1 = acc[mt][n8][1];
            float c2 = acc[mt][n8][2], c3 = acc[mt][n8][3];
            if (Cf) {
                float2 v0; v0.x = c0; v0.y = c1;
                float2 v1; v1.x = c2; v1.y = c3;
                *(float2*)(Cf + (size_t)r0 * N + col) = v0;
                *(float2*)(Cf + (size_t)r1 * N + col) = v1;
            } else {
                if (bias) {
                    const float b0 = bias[col], b1 = bias[col + 1];
                    c0 += b0; c1 += b1; c2 += b0; c3 += b1;
                }
                fp16 h0,l0,h1,l1,h2,l2,h3,l3;
                split2h(c0, h0, l0); split2h(c1, h1, l1);
                split2h(c2, h2, l2); split2h(c3, h3, l3);
                __half2 hh0 = __halves2half2(h0, h1);
                __half2 ll0 = __halves2half2(l0, l1);
                __half2 hh1 = __halves2half2(h2, h3);
                __half2 ll1 = __halves2half2(l2, l3);
                *(__half2*)(Ch + (size_t)r0 * N + col) = hh0;
                *(__half2*)(Cl + (size_t)r0 * N + col) = ll0;
                *(__half2*)(Ch + (size_t)r1 * N + col) = hh1;
                *(__half2*)(Cl + (size_t)r1 * N + col) = ll1;
            }
        }
    }
}

// ---------------------------------------------------------------------------
// 2-pass GEMM: C[M,N] = A[M,K] @ (Bh+Bl)[N,K]^T, A plain fp16 (no lo split).
// 16 warps, 4-stage cp.async pipeline (3 tiles/stage). fp32 out.
// ---------------------------------------------------------------------------
#define STG2_B (3u * TILE_B)
#define SMEM2  (4u * STG2_B)     // 192 KB

__global__ __launch_bounds__(NTH, 1)
void gemm2p(const fp16* __restrict__ Ah_,
            const fp16* __restrict__ Bh_, const fp16* __restrict__ Bl_,
            float* __restrict__ Cf, int M, int N, int K)
{
    extern __shared__ char smem_raw[];
    const uint32_t sbase = smem_to_u32(smem_raw);

    const int tid  = threadIdx.x;
    const int w    = tid >> 5;
    const int lane = tid & 31;
    const int bx = blockIdx.x, by = blockIdx.y;
    const int wm = (w >> 2) * 32;
    const int wn = (w & 3) * 32;

    const fp16* gAh = Ah_ + (size_t)by * 128 * K;
    const fp16* gBh = Bh_ + (size_t)bx * 128 * K;
    const fp16* gBl = Bl_ + (size_t)bx * 128 * K;

    float acc[2][4][4];
#pragma unroll
    for (int i = 0; i < 2; i++)
#pragma unroll
        for (int j = 0; j < 4; j++)
#pragma unroll
            for (int k = 0; k < 4; k++) acc[i][j][k] = 0.0f;

    uint32_t lso[2];
    size_t lgo[2];
#pragma unroll
    for (int i = 0; i < 2; i++) {
        int idx = tid + i * NTH;
        int row = idx >> 3;
        int u   = idx & 7;
        lso[i] = (uint32_t)row * 128u + (uint32_t)((u ^ (row & 7)) << 4);
        lgo[i] = (size_t)row * K + (size_t)u * 8;
    }

    const int NC = K >> 6;

    auto load_stage = [&](int c, int s) {
        const size_t kofs = (size_t)c << 6;
        const uint32_t sb = sbase + (uint32_t)s * STG2_B;
#pragma unroll
        for (int i = 0; i < 2; i++) {
            cp_async16(sb + 0u * TILE_B + lso[i], gAh + lgo[i] + kofs);
            cp_async16(sb + 1u * TILE_B + lso[i], gBh + lgo[i] + kofs);
            cp_async16(sb + 2u * TILE_B + lso[i], gBl + lgo[i] + kofs);
        }
    };

    load_stage(0, 0); CP_COMMIT();
    if (NC > 1) load_stage(1, 1);
    CP_COMMIT();
    if (NC > 2) load_stage(2, 2);
    CP_COMMIT();

    const int lr = lane & 15;
    const int lu = lane >> 4;

    for (int c = 0; c < NC; c++) {
        if (c + 3 < NC) load_stage(c + 3, (c + 3) & 3);
        CP_COMMIT();
        CP_WAIT(3);
        __syncthreads();

        const uint32_t st  = sbase + (uint32_t)(c & 3) * STG2_B;
        const uint32_t Ahb = st;
        const uint32_t Bhb = st + 1u * TILE_B;
        const uint32_t Blb = st + 2u * TILE_B;

#pragma unroll
        for (int ks = 0; ks < 4; ks++) {
            uint32_t ah[2][4], bh[2][4], bl[2][4];
            const int unit = ks * 2 + lu;
#pragma unroll
            for (int mt = 0; mt < 2; mt++) {
                int row = wm + mt * 16 + lr;
                uint32_t off = (uint32_t)row * 128u
                             + (uint32_t)((unit ^ (row & 7)) << 4);
                ldmx4(ah[mt], Ahb + off);
            }
#pragma unroll
            for (int nt = 0; nt < 2; nt++) {
                int row = wn + nt * 16 + lr;
                uint32_t off = (uint32_t)row * 128u
                             + (uint32_t)((unit ^ (row & 7)) << 4);
                ldmx4(bh[nt], Bhb + off);
                ldmx4(bl[nt], Blb + off);
            }
#pragma unroll
            for (int mt = 0; mt < 2; mt++) {
#pragma unroll
                for (int n8 = 0; n8 < 4; n8++) {
                    const int nt = n8 >> 1, sel = n8 & 1;
                    mma_f16(acc[mt][n8], ah[mt], bh[nt][sel], bh[nt][sel + 2]);
                    mma_f16(acc[mt][n8], ah[mt], bl[nt][sel], bl[nt][sel + 2]);
                }
            }
        }
        __syncthreads();
    }

    const int g  = lane >> 2;
    const int tc = lane & 3;
#pragma unroll
    for (int mt = 0; mt < 2; mt++) {
#pragma unroll
        for (int n8 = 0; n8 < 4; n8++) {
            const int r0 = by * 128 + wm + mt * 16 + g;
            const int r1 = r0 + 8;
            const int col = bx * 128 + wn + n8 * 8 + tc * 2;
            float2 v0; v0.x = acc[mt][n8][0]; v0.y = acc[mt][n8][1];
            float2 v1; v1.x = acc[mt][n8][2]; v1.y = acc[mt][n8][3];
            *(float2*)(Cf + (size_t)r0 * N + col) = v0;
            *(float2*)(Cf + (size_t)r1 * N + col) = v1;
        }
    }
}

// ---------------------------------------------------------------------------
// fp32 -> (hi, lo) fp16 split, vectorized x4
// ---------------------------------------------------------------------------
__global__ __launch_bounds__(256)
void split_h(const float* __restrict__ in, fp16* __restrict__ oh,
             fp16* __restrict__ ol, int n4)
{
    int i = blockIdx.x * blockDim.x + threadIdx.x;
    if (i >= n4) return;
    float4 v = ((const float4*)in)[i];
    fp16 h0,l0,h1,l1,h2,l2,h3,l3;
    split2h(v.x, h0, l0); split2h(v.y, h1, l1);
    split2h(v.z, h2, l2); split2h(v.w, h3, l3);
    __half2 ha = __halves2half2(h0, h1), hb = __halves2half2(h2, h3);
    __half2 la = __halves2half2(l0, l1), lb = __halves2half2(l2, l3);
    uint2 hu; hu.x = *(uint32_t*)&ha; hu.y = *(uint32_t*)&hb;
    uint2 lu; lu.x = *(uint32_t*)&la; lu.y = *(uint32_t*)&lb;
    ((uint2*)oh)[i] = hu;
    ((uint2*)ol)[i] = lu;
}

// ---------------------------------------------------------------------------
// in [R, C] fp32 -> out [C, R] fp16 (hi, lo) split. grid (C/32, R/32), 32x8.
// ---------------------------------------------------------------------------
__global__ __launch_bounds__(256)
void transpose_split_h(const float* __restrict__ in, fp16* __restrict__ oh,
                       fp16* __restrict__ ol, int R, int C)
{
    __shared__ float t[32][33];
    const int c0 = blockIdx.x * 32;
    const int r0 = blockIdx.y * 32;
    const int tx = threadIdx.x;
    const int ty = threadIdx.y;
#pragma unroll
    for (int j = 0; j < 32; j += 8)
        t[ty + j][tx] = in[(size_t)(r0 + ty + j) * C + c0 + tx];
    __syncthreads();
#pragma unroll
    for (int j = 0; j < 32; j += 8) {
        float v = t[tx][ty + j];
        fp16 h, l;
        split2h(v, h, l);
        size_t o = (size_t)(c0 + ty + j) * R + r0 + tx;
        oh[o] = h;
        ol[o] = l;
    }
}

// ---------------------------------------------------------------------------
// w[e] = sum_a bq[a] * Wk[a, e]   (Wk row-major [DIM, DIM])
// ---------------------------------------------------------------------------
__global__ __launch_bounds__(256)
void wvec(const float* __restrict__ Wk, const float* __restrict__ bq,
          float* __restrict__ w)
{
    int e = blockIdx.x * 256 + threadIdx.x;
    float s = 0.0f;
    for (int a = 0; a < DIM; a++)
        s += bq[a] * Wk[(size_t)a * DIM + e];
    w[e] = s;
}

// ---------------------------------------------------------------------------
// v[i] = sum_d x[i, d] * w[d]   — one warp per row
// ---------------------------------------------------------------------------
__global__ __launch_bounds__(256)
void vvec(const float* __restrict__ x, const float* __restrict__ w,
          float* __restrict__ v)
{
    const int wid = threadIdx.x >> 5;
    const int lane = threadIdx.x & 31;
    const int row = blockIdx.x * 8 + wid;
    const float* xr = x + (size_t)row * DIM;
    float s = 0.0f;
#pragma unroll
    for (int it = 0; it < 8; it++) {
        int d = (it * 32 + lane) * 4;
        float4 a = *(const float4*)(xr + d);
        float4 b = *(const float4*)(w + d);
        s += a.x * b.x + a.y * b.y + a.z * b.z + a.w * b.w;
    }
#pragma unroll
    for (int o = 16; o > 0; o >>= 1)
        s += __shfl_xor_sync(0xffffffffu, s, o);
    if (lane == 0) v[row] = s;
}

// ---------------------------------------------------------------------------
// softmax over rows of (S + 1*v^T), emit plain fp16 attn.
// ---------------------------------------------------------------------------
__global__ __launch_bounds__(256, 4)
void softmax_v(const float* __restrict__ S, const float* __restrict__ vcol,
               fp16* __restrict__ oh)
{
    const int row = blockIdx.x;
    const float* r = S + (size_t)row * N_TOK;
    const int tid = threadIdx.x;
    const int lane = tid & 31;
    const int wid = tid >> 5;

    __shared__ float red[32];

    float4 v[4];
    float mx = -CUDART_INF_F;
#pragma unroll
    for (int i = 0; i < 4; i++) {
        size_t p = (size_t)(tid + i * 256) * 4;
        v[i] = *(const float4*)(r + p);
        float4 vv = *(const float4*)(vcol + p);
        v[i].x += vv.x; v[i].y += vv.y; v[i].z += vv.z; v[i].w += vv.w;
        mx = fmaxf(mx, fmaxf(fmaxf(v[i].x, v[i].y), fmaxf(v[i].z, v[i].w)));
    }
#pragma unroll
    for (int o = 16; o > 0; o >>= 1)
        mx = fmaxf(mx, __shfl_xor_sync(0xffffffffu, mx, o));
    if (lane == 0) red[wid] = mx;
    __syncthreads();
    if (wid == 0) {
        float m = (lane < 8) ? red[lane] : -CUDART_INF_F;
#pragma unroll
        for (int o = 4; o > 0; o >>= 1)
            m = fmaxf(m, __shfl_xor_sync(0xffffffffu, m, o));
        if (lane == 0) red[0] = m;
    }
    __syncthreads();
    mx = red[0];
    __syncthreads();

    float sum = 0.0f;
#pragma unroll
    for (int i = 0; i < 4; i++) {
        v[i].x = expf(v[i].x - mx);
        v[i].y = expf(v[i].y - mx);
        v[i].z = expf(v[i].z - mx);
        v[i].w = expf(v[i].w - mx);
        sum += v[i].x + v[i].y + v[i].z + v[i].w;
    }
#pragma unroll
    for (int o = 16; o > 0; o >>= 1)
        sum += __shfl_xor_sync(0xffffffffu, sum, o);
    if (lane == 0) red[wid] = sum;
    __syncthreads();
    if (wid == 0) {
        float s = (lane < 8) ? red[lane] : 0.0f;
#pragma unroll
        for (int o = 4; o > 0; o >>= 1)
            s += __shfl_xor_sync(0xffffffffu, s, o);
        if (lane == 0) red[0] = s;
    }
    __syncthreads();
    const float inv = 1.0f / red[0];

#pragma unroll
    for (int i = 0; i < 4; i++) {
        __half2 a = __halves2half2(__float2half_rn(v[i].x * inv),
                                   __float2half_rn(v[i].y * inv));
        __half2 b = __halves2half2(__float2half_rn(v[i].z * inv),
                                   __float2half_rn(v[i].w * inv));
        uint2 u; u.x = *(uint32_t*)&a; u.y = *(uint32_t*)&b;
        size_t p = (size_t)row * N_TOK + (size_t)(tid + i * 256) * 4;
        *(uint2*)(oh + p) = u;
    }
}

// ---------------------------------------------------------------------------
// Launch
// ---------------------------------------------------------------------------
extern "C" void kernel_launch(void* const* d_in, const int* in_sizes, int n_in,
                              void* d_out, int out_size)
{
    const float* x  = (const float*)d_in[0];   // [4096, 1024]
    const float* Wq = (const float*)d_in[1];   // [1024, 1024]
    const float* bq = (const float*)d_in[2];   // [1024]
    const float* Wk = (const float*)d_in[3];   // [1024, 1024]
    const float* bk = (const float*)d_in[4];   // [1024]  (cancels in softmax)
    float* out = (float*)d_out;                // [4096, 1024]
    (void)bk;

    fp16 *xh, *xl, *xth, *xtl, *wqt, *wqtl, *wkt, *wktl, *mth, *mtl, *th, *tl, *sh;
    float *s, *wv, *vv;
    cudaGetSymbolAddress((void**)&xh,   g_xh);
    cudaGetSymbolAddress((void**)&xl,   g_xl);
    cudaGetSymbolAddress((void**)&xth,  g_xth);
    cudaGetSymbolAddress((void**)&xtl,  g_xtl);
    cudaGetSymbolAddress((void**)&wqt,  g_wqt);
    cudaGetSymbolAddress((void**)&wqtl, g_wqtl);
    cudaGetSymbolAddress((void**)&wkt,  g_wkt);
    cudaGetSymbolAddress((void**)&wktl, g_wktl);
    cudaGetSymbolAddress((void**)&mth,  g_mth);
    cudaGetSymbolAddress((void**)&mtl,  g_mtl);
    cudaGetSymbolAddress((void**)&th,   g_th);
    cudaGetSymbolAddress((void**)&tl,   g_tl);
    cudaGetSymbolAddress((void**)&sh,   g_sh);
    cudaGetSymbolAddress((void**)&s,    g_s);
    cudaGetSymbolAddress((void**)&wv,   g_w);
    cudaGetSymbolAddress((void**)&vv,   g_v);

    cudaFuncSetAttribute(gemm3p, cudaFuncAttributeMaxDynamicSharedMemorySize, SMEM3);
    cudaFuncSetAttribute(gemm2p, cudaFuncAttributeMaxDynamicSharedMemorySize, SMEM2);

    // Prep: splits, transposes, bias vectors
    {
        int n4 = N_TOK * DIM / 4;
        split_h<<<(n4 + 255) / 256, 256>>>(x, xh, xl, n4);
        transpose_split_h<<<dim3(DIM / 32, N_TOK / 32), dim3(32, 8)>>>(x, xth, xtl, N_TOK, DIM);
        transpose_split_h<<<dim3(DIM / 32, DIM / 32), dim3(32, 8)>>>(Wq, wqt, wqtl, DIM, DIM);
        transpose_split_h<<<dim3(DIM / 32, DIM / 32), dim3(32, 8)>>>(Wk, wkt, wktl, DIM, DIM);
        wvec<<<DIM / 256, 256>>>(Wk, bq, wv);
        vvec<<<N_TOK / 8, 256>>>(x, wv, vv);
    }

    // Mt = Wk^T @ Wq, split out. M=N=K=1024
    gemm3p<<<dim3(DIM / 128, DIM / 128), NTH, SMEM3>>>(
        wkt, wktl, wqt, wqtl, nullptr, nullptr, mth, mtl, DIM, DIM, DIM);

    // t = x @ M, split out. M=4096,N=1024,K=1024
    gemm3p<<<dim3(DIM / 128, N_TOK / 128), NTH, SMEM3>>>(
        xh, xl, mth, mtl, nullptr, nullptr, th, tl, N_TOK, DIM, DIM);

    // scores = t @ x^T, fp32 out. M=N=4096, K=1024
    gemm3p<<<dim3(N_TOK / 128, N_TOK / 128), NTH, SMEM3>>>(
        th, tl, xh, xl, nullptr, s, nullptr, nullptr, N_TOK, N_TOK, DIM);

    // softmax(scores + 1*v^T) -> attn fp16
    softmax_v<<<N_TOK, 256>>>(s, vv, sh);

    // out = attn @ x, 2-pass. M=4096,N=1024,K=4096
    gemm2p<<<dim3(DIM / 128, N_TOK / 128), NTH, SMEM2>>>(
        sh, xth, xtl, out, N_TOK, DIM, N_TOK);
}

// round 6
// speedup vs baseline: 5.0344x; 1.7987x over previous
#include <cuda_runtime.h>
#include <cuda_fp16.h>
#include <math_constants.h>
#include <cstdint>

#define N_TOK 4096
#define DIM   1024

typedef __half fp16;

// ---------------------------------------------------------------------------
// Scratch (device globals; no allocation allowed)
// ---------------------------------------------------------------------------
__device__ fp16  g_xh [(size_t)N_TOK * DIM];
__device__ fp16  g_xl [(size_t)N_TOK * DIM];
__device__ fp16  g_wqt[(size_t)DIM * DIM];     // Wq^T split
__device__ fp16  g_wqtl[(size_t)DIM * DIM];
__device__ fp16  g_wkt[(size_t)DIM * DIM];     // Wk^T split
__device__ fp16  g_wktl[(size_t)DIM * DIM];
__device__ fp16  g_mth[(size_t)DIM * DIM];     // (Wq^T Wk)^T split
__device__ fp16  g_mtl[(size_t)DIM * DIM];
__device__ fp16  g_th [(size_t)N_TOK * DIM];   // t = x @ M split
__device__ fp16  g_tl [(size_t)N_TOK * DIM];
__device__ float g_s  [(size_t)N_TOK * N_TOK]; // approx scores
__device__ float g_w  [DIM];
__device__ float g_v  [N_TOK];

// ---------------------------------------------------------------------------
// Helpers
// ---------------------------------------------------------------------------
__device__ __forceinline__ uint32_t smem_to_u32(const void* p) {
    uint32_t a;
    asm("{ .reg .u64 t; cvta.to.shared.u64 t, %1; cvt.u32.u64 %0, t; }"
        : "=r"(a) : "l"(p));
    return a;
}

__device__ __forceinline__ void cp_async16(uint32_t dst, const void* src) {
    asm volatile("cp.async.cg.shared.global [%0], [%1], 16;"
        :: "r"(dst), "l"(src) : "memory");
}
#define CP_COMMIT() asm volatile("cp.async.commit_group;" ::: "memory")
#define CP_WAIT(n)  asm volatile("cp.async.wait_group %0;" :: "n"(n) : "memory")

__device__ __forceinline__ void ldmx4(uint32_t r[4], uint32_t addr) {
    asm volatile("ldmatrix.sync.aligned.m8n8.x4.shared.b16 {%0,%1,%2,%3}, [%4];"
        : "=r"(r[0]), "=r"(r[1]), "=r"(r[2]), "=r"(r[3]) : "r"(addr));
}

__device__ __forceinline__ void mma_f16(float d[4], const uint32_t a[4],
                                        uint32_t b0, uint32_t b1) {
    asm volatile(
        "mma.sync.aligned.m16n8k16.row.col.f32.f16.f16.f32 "
        "{%0,%1,%2,%3}, {%4,%5,%6,%7}, {%8,%9}, {%0,%1,%2,%3};"
        : "+f"(d[0]), "+f"(d[1]), "+f"(d[2]), "+f"(d[3])
        : "r"(a[0]), "r"(a[1]), "r"(a[2]), "r"(a[3]), "r"(b0), "r"(b1));
}

__device__ __forceinline__ void split2h(float v, fp16& h, fp16& l) {
    h = __float2half_rn(v);
    l = __float2half_rn(v - __half2float(h));
}

// ---------------------------------------------------------------------------
// 3-pass split-fp16 GEMM: C[M,N] = A[M,K] @ B[N,K]^T  (fp32 effective)
// Block 128x128, BK=64, 16 warps (32x32 warp tiles), 3-stage cp.async.
// Cf != null: fp32 out.  else: (Ch, Cl) fp16 split out.
// ---------------------------------------------------------------------------
#define TILE_B   16384u
#define STG3_B   (4u * TILE_B)
#define SMEM3    (3u * STG3_B)    // 192 KB
#define NTH      512

__global__ __launch_bounds__(NTH, 1)
void gemm3p(const fp16* __restrict__ Ah_, const fp16* __restrict__ Al_,
            const fp16* __restrict__ Bh_, const fp16* __restrict__ Bl_,
            float* __restrict__ Cf, fp16* __restrict__ Ch, fp16* __restrict__ Cl,
            int M, int N, int K)
{
    extern __shared__ char smem_raw[];
    const uint32_t sbase = smem_to_u32(smem_raw);

    const int tid  = threadIdx.x;
    const int w    = tid >> 5;
    const int lane = tid & 31;
    const int bx = blockIdx.x, by = blockIdx.y;
    const int wm = (w >> 2) * 32;
    const int wn = (w & 3) * 32;

    const fp16* gAh = Ah_ + (size_t)by * 128 * K;
    const fp16* gAl = Al_ + (size_t)by * 128 * K;
    const fp16* gBh = Bh_ + (size_t)bx * 128 * K;
    const fp16* gBl = Bl_ + (size_t)bx * 128 * K;

    float acc[2][4][4];
#pragma unroll
    for (int i = 0; i < 2; i++)
#pragma unroll
        for (int j = 0; j < 4; j++)
#pragma unroll
            for (int k = 0; k < 4; k++) acc[i][j][k] = 0.0f;

    uint32_t lso[2];
    size_t lgo[2];
#pragma unroll
    for (int i = 0; i < 2; i++) {
        int idx = tid + i * NTH;
        int row = idx >> 3;
        int u   = idx & 7;
        lso[i] = (uint32_t)row * 128u + (uint32_t)((u ^ (row & 7)) << 4);
        lgo[i] = (size_t)row * K + (size_t)u * 8;
    }

    const int NC = K >> 6;

    auto load_stage = [&](int c, int s) {
        const size_t kofs = (size_t)c << 6;
        const uint32_t sb = sbase + (uint32_t)s * STG3_B;
#pragma unroll
        for (int i = 0; i < 2; i++) {
            cp_async16(sb + 0u * TILE_B + lso[i], gAh + lgo[i] + kofs);
            cp_async16(sb + 1u * TILE_B + lso[i], gAl + lgo[i] + kofs);
            cp_async16(sb + 2u * TILE_B + lso[i], gBh + lgo[i] + kofs);
            cp_async16(sb + 3u * TILE_B + lso[i], gBl + lgo[i] + kofs);
        }
    };

    load_stage(0, 0); CP_COMMIT();
    if (NC > 1) load_stage(1, 1);
    CP_COMMIT();

    const int lr = lane & 15;
    const int lu = lane >> 4;

    for (int c = 0; c < NC; c++) {
        if (c + 2 < NC) load_stage(c + 2, (c + 2) % 3);
        CP_COMMIT();
        CP_WAIT(2);
        __syncthreads();

        const uint32_t st  = sbase + (uint32_t)(c % 3) * STG3_B;
        const uint32_t Ahb = st;
        const uint32_t Alb = st + 1u * TILE_B;
        const uint32_t Bhb = st + 2u * TILE_B;
        const uint32_t Blb = st + 3u * TILE_B;

#pragma unroll
        for (int ks = 0; ks < 4; ks++) {
            uint32_t ah[2][4], al[2][4], bh[2][4], bl[2][4];
            const int unit = ks * 2 + lu;
#pragma unroll
            for (int mt = 0; mt < 2; mt++) {
                int row = wm + mt * 16 + lr;
                uint32_t off = (uint32_t)row * 128u
                             + (uint32_t)((unit ^ (row & 7)) << 4);
                ldmx4(ah[mt], Ahb + off);
                ldmx4(al[mt], Alb + off);
            }
#pragma unroll
            for (int nt = 0; nt < 2; nt++) {
                int row = wn + nt * 16 + lr;
                uint32_t off = (uint32_t)row * 128u
                             + (uint32_t)((unit ^ (row & 7)) << 4);
                ldmx4(bh[nt], Bhb + off);
                ldmx4(bl[nt], Blb + off);
            }
#pragma unroll
            for (int mt = 0; mt < 2; mt++) {
#pragma unroll
                for (int n8 = 0; n8 < 4; n8++) {
                    const int nt = n8 >> 1, sel = n8 & 1;
                    const uint32_t b0h = bh[nt][sel], b1h = bh[nt][sel + 2];
                    const uint32_t b0l = bl[nt][sel], b1l = bl[nt][sel + 2];
                    mma_f16(acc[mt][n8], ah[mt], b0h, b1h);
                    mma_f16(acc[mt][n8], ah[mt], b0l, b1l);
                    mma_f16(acc[mt][n8], al[mt], b0h, b1h);
                }
            }
        }
        __syncthreads();
    }

    const int g  = lane >> 2;
    const int tc = lane & 3;
#pragma unroll
    for (int mt = 0; mt < 2; mt++) {
#pragma unroll
        for (int n8 = 0; n8 < 4; n8++) {
            const int r0 = by * 128 + wm + mt * 16 + g;
            const int r1 = r0 + 8;
            const int col = bx * 128 + wn + n8 * 8 + tc * 2;
            float c0 = acc[mt][n8][0], c1 = acc[mt][n8][1];
            float c2 = acc[mt][n8][2], c3 = acc[mt][n8][3];
            if (Cf) {
                float2 v0; v0.x = c0; v0.y = c1;
                float2 v1; v1.x = c2; v1.y = c3;
                *(float2*)(Cf + (size_t)r0 * N + col) = v0;
                *(float2*)(Cf + (size_t)r1 * N + col) = v1;
            } else {
                fp16 h0,l0,h1,l1,h2,l2,h3,l3;
                split2h(c0, h0, l0); split2h(c1, h1, l1);
                split2h(c2, h2, l2); split2h(c3, h3, l3);
                __half2 hh0 = __halves2half2(h0, h1);
                __half2 ll0 = __halves2half2(l0, l1);
                __half2 hh1 = __halves2half2(h2, h3);
                __half2 ll1 = __halves2half2(l2, l3);
                *(__half2*)(Ch + (size_t)r0 * N + col) = hh0;
                *(__half2*)(Cl + (size_t)r0 * N + col) = ll0;
                *(__half2*)(Ch + (size_t)r1 * N + col) = hh1;
                *(__half2*)(Cl + (size_t)r1 * N + col) = ll1;
            }
        }
    }
}

// ---------------------------------------------------------------------------
// 1-pass fp16 GEMM: C[M,N] = A[M,K] @ B[N,K]^T (approx). fp32 out.
// 16 warps, 4-stage cp.async (2 tiles/stage).
// ---------------------------------------------------------------------------
#define STG1_B (2u * TILE_B)
#define SMEM1  (4u * STG1_B)     // 128 KB

__global__ __launch_bounds__(NTH, 1)
void gemm1p(const fp16* __restrict__ Ah_, const fp16* __restrict__ Bh_,
            float* __restrict__ Cf, int M, int N, int K)
{
    extern __shared__ char smem_raw[];
    const uint32_t sbase = smem_to_u32(smem_raw);

    const int tid  = threadIdx.x;
    const int w    = tid >> 5;
    const int lane = tid & 31;
    const int bx = blockIdx.x, by = blockIdx.y;
    const int wm = (w >> 2) * 32;
    const int wn = (w & 3) * 32;

    const fp16* gAh = Ah_ + (size_t)by * 128 * K;
    const fp16* gBh = Bh_ + (size_t)bx * 128 * K;

    float acc[2][4][4];
#pragma unroll
    for (int i = 0; i < 2; i++)
#pragma unroll
        for (int j = 0; j < 4; j++)
#pragma unroll
            for (int k = 0; k < 4; k++) acc[i][j][k] = 0.0f;

    uint32_t lso[2];
    size_t lgo[2];
#pragma unroll
    for (int i = 0; i < 2; i++) {
        int idx = tid + i * NTH;
        int row = idx >> 3;
        int u   = idx & 7;
        lso[i] = (uint32_t)row * 128u + (uint32_t)((u ^ (row & 7)) << 4);
        lgo[i] = (size_t)row * K + (size_t)u * 8;
    }

    const int NC = K >> 6;

    auto load_stage = [&](int c, int s) {
        const size_t kofs = (size_t)c << 6;
        const uint32_t sb = sbase + (uint32_t)s * STG1_B;
#pragma unroll
        for (int i = 0; i < 2; i++) {
            cp_async16(sb + 0u * TILE_B + lso[i], gAh + lgo[i] + kofs);
            cp_async16(sb + 1u * TILE_B + lso[i], gBh + lgo[i] + kofs);
        }
    };

    load_stage(0, 0); CP_COMMIT();
    if (NC > 1) load_stage(1, 1);
    CP_COMMIT();
    if (NC > 2) load_stage(2, 2);
    CP_COMMIT();

    const int lr = lane & 15;
    const int lu = lane >> 4;

    for (int c = 0; c < NC; c++) {
        if (c + 3 < NC) load_stage(c + 3, (c + 3) & 3);
        CP_COMMIT();
        CP_WAIT(3);
        __syncthreads();

        const uint32_t st  = sbase + (uint32_t)(c & 3) * STG1_B;
        const uint32_t Ahb = st;
        const uint32_t Bhb = st + 1u * TILE_B;

#pragma unroll
        for (int ks = 0; ks < 4; ks++) {
            uint32_t ah[2][4], bh[2][4];
            const int unit = ks * 2 + lu;
#pragma unroll
            for (int mt = 0; mt < 2; mt++) {
                int row = wm + mt * 16 + lr;
                uint32_t off = (uint32_t)row * 128u
                             + (uint32_t)((unit ^ (row & 7)) << 4);
                ldmx4(ah[mt], Ahb + off);
            }
#pragma unroll
            for (int nt = 0; nt < 2; nt++) {
                int row = wn + nt * 16 + lr;
                uint32_t off = (uint32_t)row * 128u
                             + (uint32_t)((unit ^ (row & 7)) << 4);
                ldmx4(bh[nt], Bhb + off);
            }
#pragma unroll
            for (int mt = 0; mt < 2; mt++) {
#pragma unroll
                for (int n8 = 0; n8 < 4; n8++) {
                    const int nt = n8 >> 1, sel = n8 & 1;
                    mma_f16(acc[mt][n8], ah[mt], bh[nt][sel], bh[nt][sel + 2]);
                }
            }
        }
        __syncthreads();
    }

    const int g  = lane >> 2;
    const int tc = lane & 3;
#pragma unroll
    for (int mt = 0; mt < 2; mt++) {
#pragma unroll
        for (int n8 = 0; n8 < 4; n8++) {
            const int r0 = by * 128 + wm + mt * 16 + g;
            const int r1 = r0 + 8;
            const int col = bx * 128 + wn + n8 * 8 + tc * 2;
            float2 v0; v0.x = acc[mt][n8][0]; v0.y = acc[mt][n8][1];
            float2 v1; v1.x = acc[mt][n8][2]; v1.y = acc[mt][n8][3];
            *(float2*)(Cf + (size_t)r0 * N + col) = v0;
            *(float2*)(Cf + (size_t)r1 * N + col) = v1;
        }
    }
}

// ---------------------------------------------------------------------------
// fp32 -> (hi, lo) fp16 split, vectorized x4
// ---------------------------------------------------------------------------
__global__ __launch_bounds__(256)
void split_h(const float* __restrict__ in, fp16* __restrict__ oh,
             fp16* __restrict__ ol, int n4)
{
    int i = blockIdx.x * blockDim.x + threadIdx.x;
    if (i >= n4) return;
    float4 v = ((const float4*)in)[i];
    fp16 h0,l0,h1,l1,h2,l2,h3,l3;
    split2h(v.x, h0, l0); split2h(v.y, h1, l1);
    split2h(v.z, h2, l2); split2h(v.w, h3, l3);
    __half2 ha = __halves2half2(h0, h1), hb = __halves2half2(h2, h3);
    __half2 la = __halves2half2(l0, l1), lb = __halves2half2(l2, l3);
    uint2 hu; hu.x = *(uint32_t*)&ha; hu.y = *(uint32_t*)&hb;
    uint2 lu; lu.x = *(uint32_t*)&la; lu.y = *(uint32_t*)&lb;
    ((uint2*)oh)[i] = hu;
    ((uint2*)ol)[i] = lu;
}

// ---------------------------------------------------------------------------
// in [R, C] fp32 -> out [C, R] fp16 (hi, lo) split. grid (C/32, R/32), 32x8.
// ---------------------------------------------------------------------------
__global__ __launch_bounds__(256)
void transpose_split_h(const float* __restrict__ in, fp16* __restrict__ oh,
                       fp16* __restrict__ ol, int R, int C)
{
    __shared__ float t[32][33];
    const int c0 = blockIdx.x * 32;
    const int r0 = blockIdx.y * 32;
    const int tx = threadIdx.x;
    const int ty = threadIdx.y;
#pragma unroll
    for (int j = 0; j < 32; j += 8)
        t[ty + j][tx] = in[(size_t)(r0 + ty + j) * C + c0 + tx];
    __syncthreads();
#pragma unroll
    for (int j = 0; j < 32; j += 8) {
        float v = t[tx][ty + j];
        fp16 h, l;
        split2h(v, h, l);
        size_t o = (size_t)(c0 + ty + j) * R + r0 + tx;
        oh[o] = h;
        ol[o] = l;
    }
}

// ---------------------------------------------------------------------------
// w[e] = sum_a bq[a] * Wk[a, e]
// ---------------------------------------------------------------------------
__global__ __launch_bounds__(256)
void wvec(const float* __restrict__ Wk, const float* __restrict__ bq,
          float* __restrict__ w)
{
    int e = blockIdx.x * 256 + threadIdx.x;
    float s = 0.0f;
    for (int a = 0; a < DIM; a++)
        s += bq[a] * Wk[(size_t)a * DIM + e];
    w[e] = s;
}

// ---------------------------------------------------------------------------
// v[i] = sum_d x[i, d] * w[d]
// ---------------------------------------------------------------------------
__global__ __launch_bounds__(256)
void vvec(const float* __restrict__ x, const float* __restrict__ w,
          float* __restrict__ v)
{
    const int wid = threadIdx.x >> 5;
    const int lane = threadIdx.x & 31;
    const int row = blockIdx.x * 8 + wid;
    const float* xr = x + (size_t)row * DIM;
    float s = 0.0f;
#pragma unroll
    for (int it = 0; it < 8; it++) {
        int d = (it * 32 + lane) * 4;
        float4 a = *(const float4*)(xr + d);
        float4 b = *(const float4*)(w + d);
        s += a.x * b.x + a.y * b.y + a.z * b.z + a.w * b.w;
    }
#pragma unroll
    for (int o = 16; o > 0; o >>= 1)
        s += __shfl_xor_sync(0xffffffffu, s, o);
    if (lane == 0) v[row] = s;
}

// ---------------------------------------------------------------------------
// Fused per-row: approx logits (S + v) -> threshold candidates (deterministic
// prefix-scan compaction) -> exact fp32 rescore (t_row . x_j + v_j) ->
// softmax over candidates -> out[row] = sum w_c * x[c] (fp32).
// One block per row, 256 threads.
// ---------------------------------------------------------------------------
#define CAP    1024
#define MARGIN 22.0f

__global__ __launch_bounds__(256, 2)
void fused_attn_out(const float* __restrict__ S, const float* __restrict__ vcol,
                    const fp16* __restrict__ th_, const fp16* __restrict__ tl_,
                    const float* __restrict__ x, float* __restrict__ out)
{
    const int row  = blockIdx.x;
    const int tid  = threadIdx.x;
    const int lane = tid & 31;
    const int wid  = tid >> 5;

    __shared__ __align__(16) float t_row[DIM];
    __shared__ int   cidx[CAP];
    __shared__ float cval[CAP];
    __shared__ float redF[8];
    __shared__ int   redI[16];
    __shared__ int   s_cnt;
    __shared__ float s_bcast;

    // Load exact t row (th + tl) as fp32.
    for (int d = tid; d < DIM; d += 256) {
        t_row[d] = __half2float(th_[(size_t)row * DIM + d])
                 + __half2float(tl_[(size_t)row * DIM + d]);
    }

    // Load approx logits (+ column bias v), find row max.
    const float* Sr = S + (size_t)row * N_TOK;
    float l[4][4];
    float mx = -CUDART_INF_F;
#pragma unroll
    for (int i = 0; i < 4; i++) {
        size_t p = (size_t)(tid + i * 256) * 4;
        float4 sv = *(const float4*)(Sr + p);
        float4 vv = *(const float4*)(vcol + p);
        l[i][0] = sv.x + vv.x; l[i][1] = sv.y + vv.y;
        l[i][2] = sv.z + vv.z; l[i][3] = sv.w + vv.w;
#pragma unroll
        for (int e = 0; e < 4; e++) mx = fmaxf(mx, l[i][e]);
    }
#pragma unroll
    for (int o = 16; o > 0; o >>= 1)
        mx = fmaxf(mx, __shfl_xor_sync(0xffffffffu, mx, o));
    if (lane == 0) redF[wid] = mx;
    __syncthreads();
    if (wid == 0) {
        float m = (lane < 8) ? redF[lane] : -CUDART_INF_F;
#pragma unroll
        for (int o = 4; o > 0; o >>= 1)
            m = fmaxf(m, __shfl_xor_sync(0xffffffffu, m, o));
        if (lane == 0) s_bcast = m;
    }
    __syncthreads();
    const float thr = s_bcast - MARGIN;

    // Count per-thread candidates, block exclusive prefix scan.
    int mycnt = 0;
#pragma unroll
    for (int i = 0; i < 4; i++)
#pragma unroll
        for (int e = 0; e < 4; e++)
            if (l[i][e] > thr) mycnt++;

    int inc = mycnt;
#pragma unroll
    for (int o = 1; o < 32; o <<= 1) {
        int n = __shfl_up_sync(0xffffffffu, inc, o);
        if (lane >= o) inc += n;
    }
    const int myoff_w = inc - mycnt;
    const int wtot = __shfl_sync(0xffffffffu, inc, 31);
    if (lane == 0) redI[wid] = wtot;
    __syncthreads();
    if (wid == 0 && lane < 8) {
        int v = redI[lane];
#pragma unroll
        for (int o = 1; o < 8; o <<= 1) {
            int n = __shfl_up_sync(0x000000ffu, v, o);
            if (lane >= o) v += n;
        }
        redI[8 + lane] = v - redI[lane];     // exclusive warp base
        if (lane == 7) s_cnt = (v > CAP) ? CAP : v;
    }
    __syncthreads();

    // Write candidates in deterministic (i, e, tid) order.
    int k = redI[8 + wid] + myoff_w;
#pragma unroll
    for (int i = 0; i < 4; i++) {
#pragma unroll
        for (int e = 0; e < 4; e++) {
            if (l[i][e] > thr) {
                if (k < CAP) cidx[k] = (tid + i * 256) * 4 + e;
                k++;
            }
        }
    }
    __syncthreads();

    const int cnt = s_cnt;

    // Exact rescore: warp w handles candidates w, w+8, ...
    for (int c = wid; c < cnt; c += 8) {
        const float* xj = x + (size_t)cidx[c] * DIM;
        float s = 0.0f;
#pragma unroll
        for (int it = 0; it < 8; it++) {
            int d = (it * 32 + lane) * 4;
            float4 a = *(const float4*)(&t_row[d]);
            float4 b = *(const float4*)(xj + d);
            s += a.x * b.x + a.y * b.y + a.z * b.z + a.w * b.w;
        }
#pragma unroll
        for (int o = 16; o > 0; o >>= 1)
            s += __shfl_xor_sync(0xffffffffu, s, o);
        if (lane == 0) cval[c] = s + vcol[cidx[c]];
    }
    __syncthreads();

    // Softmax over candidates (exact logits).
    float m2 = -CUDART_INF_F;
    for (int c = tid; c < cnt; c += 256) m2 = fmaxf(m2, cval[c]);
#pragma unroll
    for (int o = 16; o > 0; o >>= 1)
        m2 = fmaxf(m2, __shfl_xor_sync(0xffffffffu, m2, o));
    if (lane == 0) redF[wid] = m2;
    __syncthreads();
    if (wid == 0) {
        float m = (lane < 8) ? redF[lane] : -CUDART_INF_F;
#pragma unroll
        for (int o = 4; o > 0; o >>= 1)
            m = fmaxf(m, __shfl_xor_sync(0xffffffffu, m, o));
        if (lane == 0) s_bcast = m;
    }
    __syncthreads();
    m2 = s_bcast;
    __syncthreads();

    float sum = 0.0f;
    for (int c = tid; c < cnt; c += 256) {
        float e = expf(cval[c] - m2);
        cval[c] = e;
        sum += e;
    }
#pragma unroll
    for (int o = 16; o > 0; o >>= 1)
        sum += __shfl_xor_sync(0xffffffffu, sum, o);
    if (lane == 0) redF[wid] = sum;
    __syncthreads();
    if (wid == 0) {
        float s = (lane < 8) ? redF[lane] : 0.0f;
#pragma unroll
        for (int o = 4; o > 0; o >>= 1)
            s += __shfl_xor_sync(0xffffffffu, s, o);
        if (lane == 0) s_bcast = s;
    }
    __syncthreads();
    const float inv = 1.0f / s_bcast;

    // out[row][:] = sum_c w_c * x[idx_c][:]  — thread owns 4 columns.
    float4 acc; acc.x = 0.0f; acc.y = 0.0f; acc.z = 0.0f; acc.w = 0.0f;
    const int col = tid * 4;
    for (int c = 0; c < cnt; c++) {
        const float wc = cval[c] * inv;
        float4 xv = *(const float4*)(x + (size_t)cidx[c] * DIM + col);
        acc.x += wc * xv.x; acc.y += wc * xv.y;
        acc.z += wc * xv.z; acc.w += wc * xv.w;
    }
    *(float4*)(out + (size_t)row * DIM + col) = acc;
}

// ---------------------------------------------------------------------------
// Launch
// ---------------------------------------------------------------------------
extern "C" void kernel_launch(void* const* d_in, const int* in_sizes, int n_in,
                              void* d_out, int out_size)
{
    const float* x  = (const float*)d_in[0];   // [4096, 1024]
    const float* Wq = (const float*)d_in[1];   // [1024, 1024]
    const float* bq = (const float*)d_in[2];   // [1024]
    const float* Wk = (const float*)d_in[3];   // [1024, 1024]
    const float* bk = (const float*)d_in[4];   // [1024]  (cancels in softmax)
    float* out = (float*)d_out;                // [4096, 1024]
    (void)bk;

    fp16 *xh, *xl, *wqt, *wqtl, *wkt, *wktl, *mth, *mtl, *th, *tl;
    float *s, *wv, *vv;
    cudaGetSymbolAddress((void**)&xh,   g_xh);
    cudaGetSymbolAddress((void**)&xl,   g_xl);
    cudaGetSymbolAddress((void**)&wqt,  g_wqt);
    cudaGetSymbolAddress((void**)&wqtl, g_wqtl);
    cudaGetSymbolAddress((void**)&wkt,  g_wkt);
    cudaGetSymbolAddress((void**)&wktl, g_wktl);
    cudaGetSymbolAddress((void**)&mth,  g_mth);
    cudaGetSymbolAddress((void**)&mtl,  g_mtl);
    cudaGetSymbolAddress((void**)&th,   g_th);
    cudaGetSymbolAddress((void**)&tl,   g_tl);
    cudaGetSymbolAddress((void**)&s,    g_s);
    cudaGetSymbolAddress((void**)&wv,   g_w);
    cudaGetSymbolAddress((void**)&vv,   g_v);

    cudaFuncSetAttribute(gemm3p, cudaFuncAttributeMaxDynamicSharedMemorySize, SMEM3);
    cudaFuncSetAttribute(gemm1p, cudaFuncAttributeMaxDynamicSharedMemorySize, SMEM1);

    // Prep
    {
        int n4 = N_TOK * DIM / 4;
        split_h<<<(n4 + 255) / 256, 256>>>(x, xh, xl, n4);
        transpose_split_h<<<dim3(DIM / 32, DIM / 32), dim3(32, 8)>>>(Wq, wqt, wqtl, DIM, DIM);
        transpose_split_h<<<dim3(DIM / 32, DIM / 32), dim3(32, 8)>>>(Wk, wkt, wktl, DIM, DIM);
        wvec<<<DIM / 256, 256>>>(Wk, bq, wv);
        vvec<<<N_TOK / 8, 256>>>(x, wv, vv);
    }

    // Mt = Wk^T @ Wq, split out. M=N=K=1024
    gemm3p<<<dim3(DIM / 128, DIM / 128), NTH, SMEM3>>>(
        wkt, wktl, wqt, wqtl, nullptr, mth, mtl, DIM, DIM, DIM);

    // t = x @ M, split out. M=4096,N=1024,K=1024
    gemm3p<<<dim3(DIM / 128, N_TOK / 128), NTH, SMEM3>>>(
        xh, xl, mth, mtl, nullptr, th, tl, N_TOK, DIM, DIM);

    // approx scores = th @ xh^T (1-pass), fp32. M=N=4096, K=1024
    gemm1p<<<dim3(N_TOK / 128, N_TOK / 128), NTH, SMEM1>>>(
        th, xh, s, N_TOK, N_TOK, DIM);

    // fused: select candidates, exact rescore, softmax, sparse output
    fused_attn_out<<<N_TOK, 256>>>(s, vv, th, tl, x, out);
}